// round 2
// baseline (speedup 1.0000x reference)
#include <cuda_runtime.h>

#define B_   2
#define H_   8
#define L_   2048
#define DH_  64
#define D_   512
#define M_   (B_*L_)      // 4096
#define NQKV 1536

// Scratch (no allocations allowed)
__device__ float g_q[B_*H_*L_*DH_];
__device__ float g_k[B_*H_*L_*DH_];
__device__ float g_v[B_*H_*L_*DH_];
__device__ float g_ao[M_*D_];

// ---------------------------------------------------------------------------
// Kernel 1: QKV projection. C[m][n] = sum_k x[m][k] * w_qkv[n][k]
// Scatter into g_q/g_k/g_v with [B,H,L,Dh] layout.
// ---------------------------------------------------------------------------
__global__ __launch_bounds__(256) void qkv_kernel(const float* __restrict__ x,
                                                  const float* __restrict__ w)
{
    __shared__ float As[64][33];
    __shared__ float Bs[64][33];
    const int m0 = blockIdx.y * 64;
    const int n0 = blockIdx.x * 64;
    const int tid = threadIdx.x;
    const int tx = tid & 15, ty = tid >> 4;

    float acc[4][4] = {};

    for (int k0 = 0; k0 < D_; k0 += 32) {
        #pragma unroll
        for (int t = tid; t < 64 * 32; t += 256) {
            int r = t >> 5, c = t & 31;
            As[r][c] = x[(m0 + r) * D_ + k0 + c];
            Bs[r][c] = w[(n0 + r) * D_ + k0 + c];
        }
        __syncthreads();
        #pragma unroll
        for (int kk = 0; kk < 32; kk++) {
            float a[4], b[4];
            #pragma unroll
            for (int i = 0; i < 4; i++) a[i] = As[ty * 4 + i][kk];
            #pragma unroll
            for (int j = 0; j < 4; j++) b[j] = Bs[tx * 4 + j][kk];
            #pragma unroll
            for (int i = 0; i < 4; i++)
                #pragma unroll
                for (int j = 0; j < 4; j++)
                    acc[i][j] += a[i] * b[j];
        }
        __syncthreads();
    }

    // Scatter: tile lies fully within one of q/k/v and one head.
    const int sec = n0 / D_;            // 0=q 1=k 2=v
    const int h   = (n0 % D_) / DH_;
    float* dst = (sec == 0) ? g_q : (sec == 1) ? g_k : g_v;
    #pragma unroll
    for (int i = 0; i < 4; i++) {
        int m = m0 + ty * 4 + i;
        int b = m / L_, l = m % L_;
        #pragma unroll
        for (int j = 0; j < 4; j++) {
            int dh = tx * 4 + j;
            dst[((b * H_ + h) * L_ + l) * DH_ + dh] = acc[i][j];
        }
    }
}

// ---------------------------------------------------------------------------
// Kernel 2: flash attention with inline Gaussian bias.
// Grid: (L/64, B*H), 256 threads. Dyn smem: Qs/Ks/Vs [64][65] + pos tiles.
// ---------------------------------------------------------------------------
#define ATTN_SMEM ((3 * 64 * 65 + 256) * 4)

__global__ __launch_bounds__(256) void attn_kernel(const float* __restrict__ pos,
                                                   const float* __restrict__ log_sigma,
                                                   const float* __restrict__ gbias_p,
                                                   const int*   __restrict__ nsp)
{
    extern __shared__ float sm[];
    float* Qs   = sm;                 // [64][65]
    float* Ks   = sm + 64 * 65;       // [64][65]  (reused as P)
    float* Vs   = sm + 2 * 64 * 65;   // [64][65]
    float* qpos = sm + 3 * 64 * 65;   // [64][2]
    float* kpos = qpos + 128;         // [64][2]

    const int i0 = blockIdx.x * 64;
    const int bh = blockIdx.y;
    const int b  = bh >> 3, h = bh & 7;
    const int Ls = *nsp;
    const float gb = *gbias_p;
    const float inv2s2 = 0.5f * __expf(-2.0f * log_sigma[h]);  // 1/(2*sigma^2)
    const float scale = 0.125f;                                // 64^-0.5

    const int tid = threadIdx.x;
    const int tx = tid & 15, ty = tid >> 4;

    const float* qb = g_q + (size_t)(b * H_ + h) * L_ * DH_;
    const float* kb = g_k + (size_t)(b * H_ + h) * L_ * DH_;
    const float* vb = g_v + (size_t)(b * H_ + h) * L_ * DH_;

    // Load Q tile + q positions once
    #pragma unroll
    for (int t = tid; t < 64 * 64; t += 256) {
        int r = t >> 6, c = t & 63;
        Qs[r * 65 + c] = qb[(i0 + r) * DH_ + c];
    }
    if (tid < 64) {
        int iG = i0 + tid;
        if (iG < Ls) {
            qpos[tid * 2]     = pos[(b * Ls + iG) * 2];
            qpos[tid * 2 + 1] = pos[(b * Ls + iG) * 2 + 1];
        } else {
            qpos[tid * 2] = 0.f; qpos[tid * 2 + 1] = 0.f;
        }
    }

    float O[4][4] = {};
    float mrow[4], lrow[4];
    #pragma unroll
    for (int i = 0; i < 4; i++) { mrow[i] = -1e30f; lrow[i] = 0.f; }

    for (int j0 = 0; j0 < L_; j0 += 64) {
        __syncthreads();  // protect Ks(=P)/Vs reuse from previous iteration
        #pragma unroll
        for (int t = tid; t < 64 * 64; t += 256) {
            int r = t >> 6, c = t & 63;
            Ks[r * 65 + c] = kb[(j0 + r) * DH_ + c];
            Vs[r * 65 + c] = vb[(j0 + r) * DH_ + c];
        }
        if (tid < 64) {
            int jG = j0 + tid;
            if (jG < Ls) {
                kpos[tid * 2]     = pos[(b * Ls + jG) * 2];
                kpos[tid * 2 + 1] = pos[(b * Ls + jG) * 2 + 1];
            } else {
                kpos[tid * 2] = 0.f; kpos[tid * 2 + 1] = 0.f;
            }
        }
        __syncthreads();

        // S = Q @ K^T (4x4 micro-tile)
        float S[4][4] = {};
        #pragma unroll
        for (int kk = 0; kk < 64; kk++) {
            float a[4], bb[4];
            #pragma unroll
            for (int i = 0; i < 4; i++) a[i] = Qs[(ty * 4 + i) * 65 + kk];
            #pragma unroll
            for (int j = 0; j < 4; j++) bb[j] = Ks[(tx * 4 + j) * 65 + kk];
            #pragma unroll
            for (int i = 0; i < 4; i++)
                #pragma unroll
                for (int j = 0; j < 4; j++)
                    S[i][j] += a[i] * bb[j];
        }
        __syncthreads();  // all Ks reads done before P overwrites it

        // bias + online softmax; row stats replicated in registers across 16 lanes
        #pragma unroll
        for (int i = 0; i < 4; i++) {
            int ir = ty * 4 + i;
            int iG = i0 + ir;
            bool iin = iG < Ls;
            float px = qpos[ir * 2], py = qpos[ir * 2 + 1];
            float tmax = -1e30f;
            #pragma unroll
            for (int j = 0; j < 4; j++) {
                int jc = tx * 4 + j;
                int jG = j0 + jc;
                float bias;
                if (iin && jG < Ls) {
                    float dx = px - kpos[jc * 2];
                    float dy = py - kpos[jc * 2 + 1];
                    bias = -(dx * dx + dy * dy) * inv2s2;
                } else {
                    bias = gb;
                }
                S[i][j] = S[i][j] * scale + bias;
                tmax = fmaxf(tmax, S[i][j]);
            }
            #pragma unroll
            for (int off = 8; off; off >>= 1)
                tmax = fmaxf(tmax, __shfl_xor_sync(0xffffffffu, tmax, off));
            float mnew  = fmaxf(mrow[i], tmax);
            float alpha = __expf(mrow[i] - mnew);
            mrow[i] = mnew;
            float rsum = 0.f;
            #pragma unroll
            for (int j = 0; j < 4; j++) {
                float p = __expf(S[i][j] - mnew);
                S[i][j] = p;
                rsum += p;
            }
            #pragma unroll
            for (int off = 8; off; off >>= 1)
                rsum += __shfl_xor_sync(0xffffffffu, rsum, off);
            lrow[i] = lrow[i] * alpha + rsum;
            #pragma unroll
            for (int j = 0; j < 4; j++) O[i][j] *= alpha;
            #pragma unroll
            for (int j = 0; j < 4; j++) Ks[ir * 65 + tx * 4 + j] = S[i][j];
        }
        __syncthreads();

        // O += P @ V
        #pragma unroll
        for (int kk = 0; kk < 64; kk++) {
            float a[4], bb[4];
            #pragma unroll
            for (int i = 0; i < 4; i++) a[i] = Ks[(ty * 4 + i) * 65 + kk];
            #pragma unroll
            for (int j = 0; j < 4; j++) bb[j] = Vs[kk * 65 + tx * 4 + j];
            #pragma unroll
            for (int i = 0; i < 4; i++)
                #pragma unroll
                for (int j = 0; j < 4; j++)
                    O[i][j] += a[i] * bb[j];
        }
    }

    // normalize + write to [B, L, H*Dh]
    #pragma unroll
    for (int i = 0; i < 4; i++) {
        int iG = i0 + ty * 4 + i;
        float inv_l = 1.0f / lrow[i];
        #pragma unroll
        for (int j = 0; j < 4; j++) {
            g_ao[(size_t)(b * L_ + iG) * D_ + h * DH_ + tx * 4 + j] = O[i][j] * inv_l;
        }
    }
}

// ---------------------------------------------------------------------------
// Kernel 3: output projection. out[m][n] = sum_e ao[m][e]*w_out[n][e] + b_out[n]
// ---------------------------------------------------------------------------
__global__ __launch_bounds__(256) void outproj_kernel(const float* __restrict__ w,
                                                      const float* __restrict__ bout,
                                                      float* __restrict__ out)
{
    __shared__ float As[64][33];
    __shared__ float Bs[64][33];
    const int m0 = blockIdx.y * 64;
    const int n0 = blockIdx.x * 64;
    const int tid = threadIdx.x;
    const int tx = tid & 15, ty = tid >> 4;

    float acc[4][4] = {};

    for (int k0 = 0; k0 < D_; k0 += 32) {
        #pragma unroll
        for (int t = tid; t < 64 * 32; t += 256) {
            int r = t >> 5, c = t & 31;
            As[r][c] = g_ao[(m0 + r) * D_ + k0 + c];
            Bs[r][c] = w[(n0 + r) * D_ + k0 + c];
        }
        __syncthreads();
        #pragma unroll
        for (int kk = 0; kk < 32; kk++) {
            float a[4], b[4];
            #pragma unroll
            for (int i = 0; i < 4; i++) a[i] = As[ty * 4 + i][kk];
            #pragma unroll
            for (int j = 0; j < 4; j++) b[j] = Bs[tx * 4 + j][kk];
            #pragma unroll
            for (int i = 0; i < 4; i++)
                #pragma unroll
                for (int j = 0; j < 4; j++)
                    acc[i][j] += a[i] * b[j];
        }
        __syncthreads();
    }

    #pragma unroll
    for (int i = 0; i < 4; i++) {
        int m = m0 + ty * 4 + i;
        #pragma unroll
        for (int j = 0; j < 4; j++) {
            int n = n0 + tx * 4 + j;
            out[(size_t)m * D_ + n] = acc[i][j] + bout[n];
        }
    }
}

// ---------------------------------------------------------------------------
extern "C" void kernel_launch(void* const* d_in, const int* in_sizes, int n_in,
                              void* d_out, int out_size)
{
    const float* x     = (const float*)d_in[0];
    const float* pos   = (const float*)d_in[1];
    const float* wqkv  = (const float*)d_in[2];
    const float* wout  = (const float*)d_in[3];
    const float* bout  = (const float*)d_in[4];
    const float* lsig  = (const float*)d_in[5];
    const float* gbias = (const float*)d_in[6];
    const int*   nsp   = (const int*)d_in[7];
    float* out = (float*)d_out;

    cudaFuncSetAttribute(attn_kernel, cudaFuncAttributeMaxDynamicSharedMemorySize, ATTN_SMEM);

    qkv_kernel<<<dim3(NQKV / 64, M_ / 64), 256>>>(x, wqkv);
    attn_kernel<<<dim3(L_ / 64, B_ * H_), 256, ATTN_SMEM>>>(pos, lsig, gbias, nsp);
    outproj_kernel<<<dim3(D_ / 64, M_ / 64), 256>>>(wout, bout, out);
}

// round 3
// speedup vs baseline: 3.2244x; 3.2244x over previous
#include <cuda_runtime.h>

#define B_   2
#define H_   8
#define L_   2048
#define DH_  64
#define D_   512
#define M_   4096
#define NQKV 1536
#define QKV_STRIDE 2097152   // B*H*L*DH

// Scratch (device globals; no allocations allowed).
// q/k/v stored as tf32 bit patterns (converted once in the QKV epilogue).
__device__ unsigned g_qkv[3 * QKV_STRIDE];
__device__ float    g_ao[M_ * D_];

__device__ __forceinline__ unsigned f2tf(float x) {
    unsigned u; asm("cvt.rna.tf32.f32 %0, %1;" : "=r"(u) : "f"(x)); return u;
}

__device__ __forceinline__ void mma8(float* c,
                                     unsigned a0, unsigned a1, unsigned a2, unsigned a3,
                                     unsigned b0, unsigned b1) {
    asm volatile("mma.sync.aligned.m16n8k8.row.col.f32.tf32.tf32.f32 "
                 "{%0,%1,%2,%3}, {%4,%5,%6,%7}, {%8,%9}, {%0,%1,%2,%3};"
                 : "+f"(c[0]), "+f"(c[1]), "+f"(c[2]), "+f"(c[3])
                 : "r"(a0), "r"(a1), "r"(a2), "r"(a3), "r"(b0), "r"(b1));
}

// ---------------------------------------------------------------------------
// tf32 GEMM: C[m][n] = sum_k A[m][k] * W[n][k]   (A: M x 512, W: N x 512)
// EPI=0: scatter qkv (tf32) into g_qkv.  EPI=1: A := g_ao, write out + bias.
// CTA tile 128x128, 8 warps (4x2), warp tile 32x64.
// ---------------------------------------------------------------------------
template <int NTOT, int EPI>
__global__ __launch_bounds__(256) void gemm_tf32(const float* __restrict__ A,
                                                 const float* __restrict__ Wt,
                                                 const float* __restrict__ bias,
                                                 float* __restrict__ out)
{
    __shared__ unsigned As[128][36];
    __shared__ unsigned Bs[128][36];
    const int m0 = blockIdx.y * 128;
    const int n0 = blockIdx.x * 128;
    const int tid  = threadIdx.x;
    const int warp = tid >> 5, lane = tid & 31;
    const int g = lane >> 2, t = lane & 3;
    const int wm = warp >> 1, wn = warp & 1;

    const float* Ap = (EPI == 1) ? (const float*)g_ao : A;

    float C[2][8][4] = {};

    const int lr = tid >> 3;        // 0..31
    const int lc = (tid & 7) * 4;   // 0..28 (x4)

    for (int k0 = 0; k0 < D_; k0 += 32) {
        #pragma unroll
        for (int p = 0; p < 4; p++) {
            int r = lr + p * 32;
            float4 av = *(const float4*)&Ap[(size_t)(m0 + r) * D_ + k0 + lc];
            float4 bv = *(const float4*)&Wt[(size_t)(n0 + r) * D_ + k0 + lc];
            As[r][lc+0] = f2tf(av.x); As[r][lc+1] = f2tf(av.y);
            As[r][lc+2] = f2tf(av.z); As[r][lc+3] = f2tf(av.w);
            Bs[r][lc+0] = f2tf(bv.x); Bs[r][lc+1] = f2tf(bv.y);
            Bs[r][lc+2] = f2tf(bv.z); Bs[r][lc+3] = f2tf(bv.w);
        }
        __syncthreads();
        #pragma unroll
        for (int kk = 0; kk < 32; kk += 8) {
            unsigned a[2][4];
            #pragma unroll
            for (int mf = 0; mf < 2; mf++) {
                int rb = wm * 32 + mf * 16;
                a[mf][0] = As[rb + g    ][kk + t];
                a[mf][1] = As[rb + g + 8][kk + t];
                a[mf][2] = As[rb + g    ][kk + t + 4];
                a[mf][3] = As[rb + g + 8][kk + t + 4];
            }
            #pragma unroll
            for (int nf = 0; nf < 8; nf++) {
                int nb = wn * 64 + nf * 8;
                unsigned b0 = Bs[nb + g][kk + t];
                unsigned b1 = Bs[nb + g][kk + t + 4];
                mma8(C[0][nf], a[0][0], a[0][1], a[0][2], a[0][3], b0, b1);
                mma8(C[1][nf], a[1][0], a[1][1], a[1][2], a[1][3], b0, b1);
            }
        }
        __syncthreads();
    }

    if (EPI == 0) {
        #pragma unroll
        for (int mf = 0; mf < 2; mf++) {
            int m = m0 + wm * 32 + mf * 16;
            #pragma unroll
            for (int nf = 0; nf < 8; nf++) {
                int n   = n0 + wn * 64 + nf * 8 + 2 * t;
                int sec = n >> 9;
                int h   = (n >> 6) & 7;
                int dh  = n & 63;
                #pragma unroll
                for (int rr = 0; rr < 2; rr++) {
                    int mm = m + g + rr * 8;
                    int b  = mm >> 11;
                    int l  = mm & 2047;
                    unsigned* dst = g_qkv + (size_t)sec * QKV_STRIDE
                                  + (((b * H_ + h) * L_ + l) * DH_ + dh);
                    dst[0] = f2tf(C[mf][nf][rr * 2 + 0]);
                    dst[1] = f2tf(C[mf][nf][rr * 2 + 1]);
                }
            }
        }
    } else {
        #pragma unroll
        for (int mf = 0; mf < 2; mf++) {
            int m = m0 + wm * 32 + mf * 16;
            #pragma unroll
            for (int nf = 0; nf < 8; nf++) {
                int n = n0 + wn * 64 + nf * 8 + 2 * t;
                float b0v = bias[n], b1v = bias[n + 1];
                #pragma unroll
                for (int rr = 0; rr < 2; rr++) {
                    int mm = m + g + rr * 8;
                    float2 v;
                    v.x = C[mf][nf][rr * 2 + 0] + b0v;
                    v.y = C[mf][nf][rr * 2 + 1] + b1v;
                    *(float2*)&out[(size_t)mm * NTOT + n] = v;
                }
            }
        }
    }
}

// ---------------------------------------------------------------------------
// Flash attention, tf32 mma. CTA = 64 q rows, 4 warps (16 rows each).
// ---------------------------------------------------------------------------
#define KS_P 68
#define VS_P 72
#define PS_P 68
#define ATTN_SMEM ((64 * KS_P + 64 * VS_P + 64 * PS_P) * 4 + 2 * 64 * 8)

__global__ __launch_bounds__(128) void attn_tf32(const float* __restrict__ pos,
                                                 const float* __restrict__ log_sigma,
                                                 const float* __restrict__ gbias_p,
                                                 const int*   __restrict__ nsp)
{
    extern __shared__ unsigned smA[];
    unsigned* Ks = smA;
    unsigned* Vs = Ks + 64 * KS_P;
    unsigned* Ps = Vs + 64 * VS_P;
    float2* qpos = (float2*)(Ps + 64 * PS_P);
    float2* kpos = qpos + 64;

    const int i0 = blockIdx.x * 64;
    const int bh = blockIdx.y;
    const int b  = bh >> 3, h = bh & 7;
    const int Ls = *nsp;
    const float gb = *gbias_p;
    const float inv2s2 = 0.5f * __expf(-2.0f * log_sigma[h]);
    const float scale  = 0.125f;

    const int tid  = threadIdx.x;
    const int warp = tid >> 5, lane = tid & 31;
    const int g = lane >> 2, t = lane & 3;
    const int wr = warp * 16;

    const unsigned* qb = g_qkv + 0 * (size_t)QKV_STRIDE + (size_t)(b * H_ + h) * L_ * DH_;
    const unsigned* kb = g_qkv + 1 * (size_t)QKV_STRIDE + (size_t)(b * H_ + h) * L_ * DH_;
    const unsigned* vb = g_qkv + 2 * (size_t)QKV_STRIDE + (size_t)(b * H_ + h) * L_ * DH_;

    // Stage Q into Ps (coalesced), load q positions
    {
        const int lr = tid >> 4;
        const int lc = (tid & 15) * 4;
        #pragma unroll
        for (int p = 0; p < 8; p++) {
            int r = lr + p * 8;
            *(uint4*)&Ps[r * PS_P + lc] = *(const uint4*)&qb[(size_t)(i0 + r) * DH_ + lc];
        }
    }
    if (tid < 64) {
        int iG = i0 + tid;
        float2 v = make_float2(0.f, 0.f);
        if (iG < Ls) v = *(const float2*)&pos[(size_t)(b * Ls + iG) * 2];
        qpos[tid] = v;
    }
    __syncthreads();

    // Q fragments resident in registers for whole kernel
    unsigned qf[8][4];
    #pragma unroll
    for (int kf = 0; kf < 8; kf++) {
        int kb8 = kf * 8;
        qf[kf][0] = Ps[(wr + g    ) * PS_P + kb8 + t];
        qf[kf][1] = Ps[(wr + g + 8) * PS_P + kb8 + t];
        qf[kf][2] = Ps[(wr + g    ) * PS_P + kb8 + t + 4];
        qf[kf][3] = Ps[(wr + g + 8) * PS_P + kb8 + t + 4];
    }

    float qx0, qy0, qx1, qy1; bool iin0, iin1;
    {
        int r0 = i0 + wr + g;
        float2 p0 = qpos[wr + g], p1 = qpos[wr + g + 8];
        qx0 = p0.x; qy0 = p0.y; qx1 = p1.x; qy1 = p1.y;
        iin0 = r0 < Ls; iin1 = (r0 + 8) < Ls;
    }

    float O[8][4] = {};
    float m0 = -1e30f, m1 = -1e30f, l0 = 0.f, l1 = 0.f;

    for (int j0 = 0; j0 < L_; j0 += 64) {
        __syncthreads();
        {
            const int lr = tid >> 4;
            const int lc = (tid & 15) * 4;
            #pragma unroll
            for (int p = 0; p < 8; p++) {
                int r = lr + p * 8;
                *(uint4*)&Ks[r * KS_P + lc] = *(const uint4*)&kb[(size_t)(j0 + r) * DH_ + lc];
                *(uint4*)&Vs[r * VS_P + lc] = *(const uint4*)&vb[(size_t)(j0 + r) * DH_ + lc];
            }
            if (tid < 64) {
                int jG = j0 + tid;
                float2 v = make_float2(0.f, 0.f);
                if (jG < Ls) v = *(const float2*)&pos[(size_t)(b * Ls + jG) * 2];
                kpos[tid] = v;
            }
        }
        __syncthreads();

        // S = Q K^T
        float S[8][4] = {};
        #pragma unroll
        for (int nf = 0; nf < 8; nf++) {
            #pragma unroll
            for (int kf = 0; kf < 8; kf++) {
                unsigned b0 = Ks[(nf * 8 + g) * KS_P + kf * 8 + t];
                unsigned b1 = Ks[(nf * 8 + g) * KS_P + kf * 8 + t + 4];
                mma8(S[nf], qf[kf][0], qf[kf][1], qf[kf][2], qf[kf][3], b0, b1);
            }
        }

        // Bias + online softmax on C fragments
        float mx0 = -1e30f, mx1 = -1e30f;
        #pragma unroll
        for (int nf = 0; nf < 8; nf++) {
            int c0 = nf * 8 + 2 * t;
            int jg0 = j0 + c0;
            float2 kp0 = kpos[c0], kp1 = kpos[c0 + 1];
            bool jin0 = jg0 < Ls, jin1 = (jg0 + 1) < Ls;
            float bias00, bias01, bias10, bias11;
            { float dx = qx0 - kp0.x, dy = qy0 - kp0.y;
              bias00 = (iin0 && jin0) ? -(dx*dx + dy*dy) * inv2s2 : gb; }
            { float dx = qx0 - kp1.x, dy = qy0 - kp1.y;
              bias01 = (iin0 && jin1) ? -(dx*dx + dy*dy) * inv2s2 : gb; }
            { float dx = qx1 - kp0.x, dy = qy1 - kp0.y;
              bias10 = (iin1 && jin0) ? -(dx*dx + dy*dy) * inv2s2 : gb; }
            { float dx = qx1 - kp1.x, dy = qy1 - kp1.y;
              bias11 = (iin1 && jin1) ? -(dx*dx + dy*dy) * inv2s2 : gb; }
            S[nf][0] = fmaf(S[nf][0], scale, bias00);
            S[nf][1] = fmaf(S[nf][1], scale, bias01);
            S[nf][2] = fmaf(S[nf][2], scale, bias10);
            S[nf][3] = fmaf(S[nf][3], scale, bias11);
            mx0 = fmaxf(mx0, fmaxf(S[nf][0], S[nf][1]));
            mx1 = fmaxf(mx1, fmaxf(S[nf][2], S[nf][3]));
        }
        mx0 = fmaxf(mx0, __shfl_xor_sync(0xffffffffu, mx0, 1));
        mx0 = fmaxf(mx0, __shfl_xor_sync(0xffffffffu, mx0, 2));
        mx1 = fmaxf(mx1, __shfl_xor_sync(0xffffffffu, mx1, 1));
        mx1 = fmaxf(mx1, __shfl_xor_sync(0xffffffffu, mx1, 2));
        float mn0 = fmaxf(m0, mx0), mn1 = fmaxf(m1, mx1);
        float a0 = __expf(m0 - mn0), a1 = __expf(m1 - mn1);
        m0 = mn0; m1 = mn1;
        float s0 = 0.f, s1 = 0.f;
        #pragma unroll
        for (int nf = 0; nf < 8; nf++) {
            S[nf][0] = __expf(S[nf][0] - m0);
            S[nf][1] = __expf(S[nf][1] - m0);
            S[nf][2] = __expf(S[nf][2] - m1);
            S[nf][3] = __expf(S[nf][3] - m1);
            s0 += S[nf][0] + S[nf][1];
            s1 += S[nf][2] + S[nf][3];
        }
        s0 += __shfl_xor_sync(0xffffffffu, s0, 1);
        s0 += __shfl_xor_sync(0xffffffffu, s0, 2);
        s1 += __shfl_xor_sync(0xffffffffu, s1, 1);
        s1 += __shfl_xor_sync(0xffffffffu, s1, 2);
        l0 = l0 * a0 + s0; l1 = l1 * a1 + s1;
        #pragma unroll
        for (int df = 0; df < 8; df++) {
            O[df][0] *= a0; O[df][1] *= a0; O[df][2] *= a1; O[df][3] *= a1;
        }

        // P -> warp-private smem region (tf32), reload as A fragments
        __syncwarp();
        #pragma unroll
        for (int nf = 0; nf < 8; nf++) {
            int c0 = nf * 8 + 2 * t;
            Ps[(wr + g    ) * PS_P + c0    ] = f2tf(S[nf][0]);
            Ps[(wr + g    ) * PS_P + c0 + 1] = f2tf(S[nf][1]);
            Ps[(wr + g + 8) * PS_P + c0    ] = f2tf(S[nf][2]);
            Ps[(wr + g + 8) * PS_P + c0 + 1] = f2tf(S[nf][3]);
        }
        __syncwarp();

        // O += P V
        #pragma unroll
        for (int kf = 0; kf < 8; kf++) {
            unsigned pa0 = Ps[(wr + g    ) * PS_P + kf * 8 + t];
            unsigned pa1 = Ps[(wr + g + 8) * PS_P + kf * 8 + t];
            unsigned pa2 = Ps[(wr + g    ) * PS_P + kf * 8 + t + 4];
            unsigned pa3 = Ps[(wr + g + 8) * PS_P + kf * 8 + t + 4];
            #pragma unroll
            for (int df = 0; df < 8; df++) {
                unsigned b0 = Vs[(kf * 8 + t    ) * VS_P + df * 8 + g];
                unsigned b1 = Vs[(kf * 8 + t + 4) * VS_P + df * 8 + g];
                mma8(O[df], pa0, pa1, pa2, pa3, b0, b1);
            }
        }
    }

    // Normalize and write to [B, L, H*Dh]
    float il0 = 1.f / l0, il1 = 1.f / l1;
    int r0 = i0 + wr + g, r1 = r0 + 8;
    #pragma unroll
    for (int df = 0; df < 8; df++) {
        int dh = df * 8 + 2 * t;
        float2 v0 = make_float2(O[df][0] * il0, O[df][1] * il0);
        float2 v1 = make_float2(O[df][2] * il1, O[df][3] * il1);
        *(float2*)&g_ao[(size_t)(b * L_ + r0) * D_ + h * DH_ + dh] = v0;
        *(float2*)&g_ao[(size_t)(b * L_ + r1) * D_ + h * DH_ + dh] = v1;
    }
}

// ---------------------------------------------------------------------------
extern "C" void kernel_launch(void* const* d_in, const int* in_sizes, int n_in,
                              void* d_out, int out_size)
{
    const float* x     = (const float*)d_in[0];
    const float* pos   = (const float*)d_in[1];
    const float* wqkv  = (const float*)d_in[2];
    const float* wout  = (const float*)d_in[3];
    const float* bout  = (const float*)d_in[4];
    const float* lsig  = (const float*)d_in[5];
    const float* gbias = (const float*)d_in[6];
    const int*   nsp   = (const int*)d_in[7];
    float* out = (float*)d_out;

    cudaFuncSetAttribute(attn_tf32, cudaFuncAttributeMaxDynamicSharedMemorySize, ATTN_SMEM);

    gemm_tf32<NQKV, 0><<<dim3(NQKV / 128, M_ / 128), 256>>>(x, wqkv, nullptr, nullptr);
    attn_tf32<<<dim3(L_ / 64, B_ * H_), 128, ATTN_SMEM>>>(pos, lsig, gbias, nsp);
    gemm_tf32<D_, 1><<<dim3(D_ / 128, M_ / 128), 256>>>(nullptr, wout, bout, out);
}

// round 4
// speedup vs baseline: 3.5849x; 1.1118x over previous
#include <cuda_runtime.h>

#define B_   2
#define H_   8
#define L_   2048
#define DH_  64
#define D_   512
#define M_   4096
#define NQKV 1536
#define QKV_STRIDE 2097152   // B*H*L*DH

// q,k plain [B,H,L,Dh]; v transposed per 64-row tile: [B,H,L/64,Dh,64]. tf32 bits.
__device__ unsigned g_qkv[3 * QKV_STRIDE];
__device__ float    g_ao[M_ * D_];

__device__ __forceinline__ unsigned f2tf(float x) {
    unsigned u; asm("cvt.rna.tf32.f32 %0, %1;" : "=r"(u) : "f"(x)); return u;
}
__device__ __forceinline__ unsigned sptr(const void* p) {
    return (unsigned)__cvta_generic_to_shared(p);
}
#define CP16(d, s) asm volatile("cp.async.cg.shared.global [%0], [%1], 16;" :: "r"(d), "l"(s) : "memory")
#define CP8Z(d, s, sz) asm volatile("cp.async.ca.shared.global [%0], [%1], 8, %2;" :: "r"(d), "l"(s), "r"(sz) : "memory")
__device__ __forceinline__ void cp_commit() { asm volatile("cp.async.commit_group;" ::: "memory"); }
__device__ __forceinline__ void cp_wait0()  { asm volatile("cp.async.wait_group 0;" ::: "memory"); }
__device__ __forceinline__ void cp_wait1()  { asm volatile("cp.async.wait_group 1;" ::: "memory"); }

__device__ __forceinline__ void mma8(float* c,
                                     unsigned a0, unsigned a1, unsigned a2, unsigned a3,
                                     unsigned b0, unsigned b1) {
    asm volatile("mma.sync.aligned.m16n8k8.row.col.f32.tf32.tf32.f32 "
                 "{%0,%1,%2,%3}, {%4,%5,%6,%7}, {%8,%9}, {%0,%1,%2,%3};"
                 : "+f"(c[0]), "+f"(c[1]), "+f"(c[2]), "+f"(c[3])
                 : "r"(a0), "r"(a1), "r"(a2), "r"(a3), "r"(b0), "r"(b1));
}

// ---------------------------------------------------------------------------
// tf32 GEMM, cp.async double-buffered. C[m][n] = sum_k A[m][k]*W[n][k].
// EPI=0: scatter qkv (q,k plain; v transposed). EPI=1: A := g_ao, out + bias.
// ---------------------------------------------------------------------------
#define GP 36
#define GEMM_SMEM (2 * 2 * 128 * GP * 4)

template <int NTOT, int EPI>
__global__ __launch_bounds__(256, 2) void gemm_tf32(const float* __restrict__ A,
                                                    const float* __restrict__ Wt,
                                                    const float* __restrict__ bias,
                                                    float* __restrict__ out)
{
    extern __shared__ float gsm[];
    float* As = gsm;                 // [2][128][GP]
    float* Bs = gsm + 2 * 128 * GP;  // [2][128][GP]

    const int m0 = blockIdx.y * 128;
    const int n0 = blockIdx.x * 128;
    const int tid  = threadIdx.x;
    const int warp = tid >> 5, lane = tid & 31;
    const int g = lane >> 2, t = lane & 3;
    const int wm = warp >> 1, wn = warp & 1;

    const float* Ap = (EPI == 1) ? (const float*)g_ao : A;

    float C[2][8][4] = {};

    // staging: 128 rows x 32 floats = 1024 x 16B chunks, 4 per thread (A and B)
    auto issue = [&](int ki, int buf) {
        int k0 = ki * 32;
        float* Ad = As + buf * 128 * GP;
        float* Bd = Bs + buf * 128 * GP;
        #pragma unroll
        for (int p = 0; p < 4; p++) {
            int c = tid + p * 256;
            int r = c >> 3, col = (c & 7) * 4;
            CP16(sptr(&Ad[r * GP + col]), &Ap[(size_t)(m0 + r) * D_ + k0 + col]);
            CP16(sptr(&Bd[r * GP + col]), &Wt[(size_t)(n0 + r) * D_ + k0 + col]);
        }
    };

    issue(0, 0);
    cp_commit();

    for (int ki = 0; ki < 16; ki++) {
        int buf = ki & 1;
        __syncthreads();
        if (ki + 1 < 16) { issue(ki + 1, buf ^ 1); cp_commit(); cp_wait1(); }
        else             { cp_wait0(); }
        __syncthreads();

        const float* Af = As + buf * 128 * GP;
        const float* Bf = Bs + buf * 128 * GP;
        #pragma unroll
        for (int kk = 0; kk < 32; kk += 8) {
            unsigned a[2][4];
            #pragma unroll
            for (int mf = 0; mf < 2; mf++) {
                int rb = wm * 32 + mf * 16;
                a[mf][0] = f2tf(Af[(rb + g    ) * GP + kk + t]);
                a[mf][1] = f2tf(Af[(rb + g + 8) * GP + kk + t]);
                a[mf][2] = f2tf(Af[(rb + g    ) * GP + kk + t + 4]);
                a[mf][3] = f2tf(Af[(rb + g + 8) * GP + kk + t + 4]);
            }
            #pragma unroll
            for (int nf = 0; nf < 8; nf++) {
                int nb = wn * 64 + nf * 8;
                unsigned b0 = f2tf(Bf[(nb + g) * GP + kk + t]);
                unsigned b1 = f2tf(Bf[(nb + g) * GP + kk + t + 4]);
                mma8(C[0][nf], a[0][0], a[0][1], a[0][2], a[0][3], b0, b1);
                mma8(C[1][nf], a[1][0], a[1][1], a[1][2], a[1][3], b0, b1);
            }
        }
    }

    if (EPI == 0) {
        #pragma unroll
        for (int mf = 0; mf < 2; mf++) {
            int m = m0 + wm * 32 + mf * 16;
            #pragma unroll
            for (int nf = 0; nf < 8; nf++) {
                int n   = n0 + wn * 64 + nf * 8 + 2 * t;
                int sec = n >> 9;
                int h   = (n >> 6) & 7;
                int dh  = n & 63;
                #pragma unroll
                for (int rr = 0; rr < 2; rr++) {
                    int mm = m + g + rr * 8;
                    int b  = mm >> 11;
                    int l  = mm & 2047;
                    unsigned v0 = f2tf(C[mf][nf][rr * 2 + 0]);
                    unsigned v1 = f2tf(C[mf][nf][rr * 2 + 1]);
                    if (sec < 2) {
                        unsigned* dst = g_qkv + (size_t)sec * QKV_STRIDE
                                      + (((b * H_ + h) * L_ + l) * DH_ + dh);
                        dst[0] = v0; dst[1] = v1;
                    } else {
                        unsigned* vb2 = g_qkv + 2 * (size_t)QKV_STRIDE
                                      + (size_t)(b * H_ + h) * L_ * DH_
                                      + (l >> 6) * 4096 + (l & 63);
                        vb2[(size_t)dh * 64]       = v0;
                        vb2[(size_t)(dh + 1) * 64] = v1;
                    }
                }
            }
        }
    } else {
        #pragma unroll
        for (int mf = 0; mf < 2; mf++) {
            int m = m0 + wm * 32 + mf * 16;
            #pragma unroll
            for (int nf = 0; nf < 8; nf++) {
                int n = n0 + wn * 64 + nf * 8 + 2 * t;
                float b0v = bias[n], b1v = bias[n + 1];
                #pragma unroll
                for (int rr = 0; rr < 2; rr++) {
                    int mm = m + g + rr * 8;
                    float2 v;
                    v.x = C[mf][nf][rr * 2 + 0] + b0v;
                    v.y = C[mf][nf][rr * 2 + 1] + b1v;
                    *(float2*)&out[(size_t)mm * NTOT + n] = v;
                }
            }
        }
    }
}

// ---------------------------------------------------------------------------
// Flash attention, tf32 mma, 128 q-rows / 8 warps, cp.async double-buffered KV.
// ---------------------------------------------------------------------------
#define KP 68
#define ATTN_SMEM ((4 * 64 * KP + 128 * KP) * 4 + 128 * 8 + 2 * 64 * 8)

__global__ __launch_bounds__(256, 2) void attn_tf32(const float* __restrict__ pos,
                                                    const float* __restrict__ log_sigma,
                                                    const float* __restrict__ gbias_p,
                                                    const int*   __restrict__ nsp)
{
    extern __shared__ unsigned smA[];
    unsigned* Ks = smA;                   // [2][64][KP]
    unsigned* Vs = smA + 2 * 64 * KP;     // [2][64][KP]  (V^T tiles)
    unsigned* Ps = smA + 4 * 64 * KP;     // [128][KP]  (Q staging, then P)
    float2* qpos = (float2*)(Ps + 128 * KP);   // 128
    float2* kpos = qpos + 128;                 // [2][64]

    const int i0 = blockIdx.x * 128;
    const int bh = blockIdx.y;
    const int b  = bh >> 3, h = bh & 7;
    const int Ls = *nsp;
    const float gb = *gbias_p;
    const float inv2s2 = 0.5f * __expf(-2.0f * log_sigma[h]);
    const float scale  = 0.125f;

    const int tid  = threadIdx.x;
    const int warp = tid >> 5, lane = tid & 31;
    const int g = lane >> 2, t = lane & 3;
    const int wr = warp * 16;

    const unsigned* qb = g_qkv + 0 * (size_t)QKV_STRIDE + (size_t)(b * H_ + h) * L_ * DH_;
    const unsigned* kb = g_qkv + 1 * (size_t)QKV_STRIDE + (size_t)(b * H_ + h) * L_ * DH_;
    const unsigned* vb = g_qkv + 2 * (size_t)QKV_STRIDE + (size_t)(b * H_ + h) * L_ * DH_;

    // Stage Q tile (128x64) into Ps
    #pragma unroll
    for (int p = 0; p < 8; p++) {
        int c = tid + p * 256;
        int r = c >> 4, c4 = (c & 15) * 4;
        *(uint4*)&Ps[r * KP + c4] = *(const uint4*)&qb[(size_t)(i0 + r) * DH_ + c4];
    }
    if (tid < 128) {
        int iG = i0 + tid;
        float2 v = make_float2(0.f, 0.f);
        if (iG < Ls) v = *(const float2*)&pos[(size_t)(b * Ls + iG) * 2];
        qpos[tid] = v;
    }
    __syncthreads();

    unsigned qf[8][4];
    #pragma unroll
    for (int kf = 0; kf < 8; kf++) {
        qf[kf][0] = Ps[(wr + g    ) * KP + kf * 8 + t];
        qf[kf][1] = Ps[(wr + g + 8) * KP + kf * 8 + t];
        qf[kf][2] = Ps[(wr + g    ) * KP + kf * 8 + t + 4];
        qf[kf][3] = Ps[(wr + g + 8) * KP + kf * 8 + t + 4];
    }

    float qx0, qy0, qx1, qy1; bool iin0, iin1;
    {
        int r0 = i0 + wr + g;
        float2 p0 = qpos[wr + g], p1 = qpos[wr + g + 8];
        qx0 = p0.x; qy0 = p0.y; qx1 = p1.x; qy1 = p1.y;
        iin0 = r0 < Ls; iin1 = (r0 + 8) < Ls;
    }

    auto issue = [&](int jt, int buf) {
        const unsigned* kt = kb + (size_t)jt * 64 * 64;
        const unsigned* vt = vb + (size_t)jt * 4096;
        unsigned* Kd = Ks + buf * 64 * KP;
        unsigned* Vd = Vs + buf * 64 * KP;
        #pragma unroll
        for (int p = 0; p < 4; p++) {
            int c = tid + p * 256;
            int r = c >> 4, c4 = (c & 15) * 4;
            CP16(sptr(&Kd[r * KP + c4]), kt + r * 64 + c4);
            CP16(sptr(&Vd[r * KP + c4]), vt + r * 64 + c4);
        }
        if (tid < 64) {
            int jG = jt * 64 + tid;
            CP8Z(sptr(&kpos[buf * 64 + tid]), &pos[(size_t)(b * Ls + jG) * 2],
                 (jG < Ls) ? 8u : 0u);
        }
    };

    float O[8][4] = {};
    float m0 = -1e30f, m1 = -1e30f, l0 = 0.f, l1 = 0.f;

    issue(0, 0);
    cp_commit();

    for (int jt = 0; jt < 32; jt++) {
        int buf = jt & 1;
        __syncthreads();   // readers of buf^1 (tile jt-1) done
        if (jt + 1 < 32) { issue(jt + 1, buf ^ 1); cp_commit(); cp_wait1(); }
        else             { cp_wait0(); }
        __syncthreads();

        const unsigned* Kf = Ks + buf * 64 * KP;
        const unsigned* Vf = Vs + buf * 64 * KP;
        const float2*   kp = kpos + buf * 64;
        const int j0 = jt * 64;

        // S = Q K^T
        float S[8][4] = {};
        #pragma unroll
        for (int nf = 0; nf < 8; nf++) {
            #pragma unroll
            for (int kf = 0; kf < 8; kf++) {
                unsigned b0 = Kf[(nf * 8 + g) * KP + kf * 8 + t];
                unsigned b1 = Kf[(nf * 8 + g) * KP + kf * 8 + t + 4];
                mma8(S[nf], qf[kf][0], qf[kf][1], qf[kf][2], qf[kf][3], b0, b1);
            }
        }

        // Bias + online softmax
        float mx0 = -1e30f, mx1 = -1e30f;
        #pragma unroll
        for (int nf = 0; nf < 8; nf++) {
            int c0 = nf * 8 + 2 * t;
            int jg0 = j0 + c0;
            float2 kp0 = kp[c0], kp1 = kp[c0 + 1];
            bool jin0 = jg0 < Ls, jin1 = (jg0 + 1) < Ls;
            float bias00, bias01, bias10, bias11;
            { float dx = qx0 - kp0.x, dy = qy0 - kp0.y;
              bias00 = (iin0 && jin0) ? -(dx*dx + dy*dy) * inv2s2 : gb; }
            { float dx = qx0 - kp1.x, dy = qy0 - kp1.y;
              bias01 = (iin0 && jin1) ? -(dx*dx + dy*dy) * inv2s2 : gb; }
            { float dx = qx1 - kp0.x, dy = qy1 - kp0.y;
              bias10 = (iin1 && jin0) ? -(dx*dx + dy*dy) * inv2s2 : gb; }
            { float dx = qx1 - kp1.x, dy = qy1 - kp1.y;
              bias11 = (iin1 && jin1) ? -(dx*dx + dy*dy) * inv2s2 : gb; }
            S[nf][0] = fmaf(S[nf][0], scale, bias00);
            S[nf][1] = fmaf(S[nf][1], scale, bias01);
            S[nf][2] = fmaf(S[nf][2], scale, bias10);
            S[nf][3] = fmaf(S[nf][3], scale, bias11);
            mx0 = fmaxf(mx0, fmaxf(S[nf][0], S[nf][1]));
            mx1 = fmaxf(mx1, fmaxf(S[nf][2], S[nf][3]));
        }
        mx0 = fmaxf(mx0, __shfl_xor_sync(0xffffffffu, mx0, 1));
        mx0 = fmaxf(mx0, __shfl_xor_sync(0xffffffffu, mx0, 2));
        mx1 = fmaxf(mx1, __shfl_xor_sync(0xffffffffu, mx1, 1));
        mx1 = fmaxf(mx1, __shfl_xor_sync(0xffffffffu, mx1, 2));
        float mn0 = fmaxf(m0, mx0), mn1 = fmaxf(m1, mx1);
        float a0 = __expf(m0 - mn0), a1 = __expf(m1 - mn1);
        m0 = mn0; m1 = mn1;
        float s0 = 0.f, s1 = 0.f;
        #pragma unroll
        for (int nf = 0; nf < 8; nf++) {
            S[nf][0] = __expf(S[nf][0] - m0);
            S[nf][1] = __expf(S[nf][1] - m0);
            S[nf][2] = __expf(S[nf][2] - m1);
            S[nf][3] = __expf(S[nf][3] - m1);
            s0 += S[nf][0] + S[nf][1];
            s1 += S[nf][2] + S[nf][3];
        }
        s0 += __shfl_xor_sync(0xffffffffu, s0, 1);
        s0 += __shfl_xor_sync(0xffffffffu, s0, 2);
        s1 += __shfl_xor_sync(0xffffffffu, s1, 1);
        s1 += __shfl_xor_sync(0xffffffffu, s1, 2);
        l0 = l0 * a0 + s0; l1 = l1 * a1 + s1;
        #pragma unroll
        for (int df = 0; df < 8; df++) {
            O[df][0] *= a0; O[df][1] *= a0; O[df][2] *= a1; O[df][3] *= a1;
        }

        // P -> warp-private smem region (tf32), reload as A fragments
        __syncwarp();
        #pragma unroll
        for (int nf = 0; nf < 8; nf++) {
            int c0 = nf * 8 + 2 * t;
            Ps[(wr + g    ) * KP + c0    ] = f2tf(S[nf][0]);
            Ps[(wr + g    ) * KP + c0 + 1] = f2tf(S[nf][1]);
            Ps[(wr + g + 8) * KP + c0    ] = f2tf(S[nf][2]);
            Ps[(wr + g + 8) * KP + c0 + 1] = f2tf(S[nf][3]);
        }
        __syncwarp();

        // O += P V   (V^T tile: rows = dh, cols = key)
        #pragma unroll
        for (int kf = 0; kf < 8; kf++) {
            unsigned pa0 = Ps[(wr + g    ) * KP + kf * 8 + t];
            unsigned pa1 = Ps[(wr + g + 8) * KP + kf * 8 + t];
            unsigned pa2 = Ps[(wr + g    ) * KP + kf * 8 + t + 4];
            unsigned pa3 = Ps[(wr + g + 8) * KP + kf * 8 + t + 4];
            #pragma unroll
            for (int df = 0; df < 8; df++) {
                unsigned b0 = Vf[(df * 8 + g) * KP + kf * 8 + t];
                unsigned b1 = Vf[(df * 8 + g) * KP + kf * 8 + t + 4];
                mma8(O[df], pa0, pa1, pa2, pa3, b0, b1);
            }
        }
    }

    // Normalize and write to [B, L, H*Dh]
    float il0 = 1.f / l0, il1 = 1.f / l1;
    int r0 = i0 + wr + g, r1 = r0 + 8;
    #pragma unroll
    for (int df = 0; df < 8; df++) {
        int dh = df * 8 + 2 * t;
        float2 v0 = make_float2(O[df][0] * il0, O[df][1] * il0);
        float2 v1 = make_float2(O[df][2] * il1, O[df][3] * il1);
        *(float2*)&g_ao[(size_t)(b * L_ + r0) * D_ + h * DH_ + dh] = v0;
        *(float2*)&g_ao[(size_t)(b * L_ + r1) * D_ + h * DH_ + dh] = v1;
    }
}

// ---------------------------------------------------------------------------
extern "C" void kernel_launch(void* const* d_in, const int* in_sizes, int n_in,
                              void* d_out, int out_size)
{
    const float* x     = (const float*)d_in[0];
    const float* pos   = (const float*)d_in[1];
    const float* wqkv  = (const float*)d_in[2];
    const float* wout  = (const float*)d_in[3];
    const float* bout  = (const float*)d_in[4];
    const float* lsig  = (const float*)d_in[5];
    const float* gbias = (const float*)d_in[6];
    const int*   nsp   = (const int*)d_in[7];
    float* out = (float*)d_out;

    cudaFuncSetAttribute(attn_tf32, cudaFuncAttributeMaxDynamicSharedMemorySize, ATTN_SMEM);
    cudaFuncSetAttribute(gemm_tf32<NQKV, 0>, cudaFuncAttributeMaxDynamicSharedMemorySize, GEMM_SMEM);
    cudaFuncSetAttribute(gemm_tf32<D_, 1>, cudaFuncAttributeMaxDynamicSharedMemorySize, GEMM_SMEM);

    gemm_tf32<NQKV, 0><<<dim3(NQKV / 128, M_ / 128), 256, GEMM_SMEM>>>(x, wqkv, nullptr, nullptr);
    attn_tf32<<<dim3(L_ / 128, B_ * H_), 256, ATTN_SMEM>>>(pos, lsig, gbias, nsp);
    gemm_tf32<D_, 1><<<dim3(D_ / 128, M_ / 128), 256, GEMM_SMEM>>>(nullptr, wout, bout, out);
}

// round 7
// speedup vs baseline: 3.6487x; 1.0178x over previous
#include <cuda_runtime.h>

#define B_   2
#define H_   8
#define L_   2048
#define DH_  64
#define D_   512
#define M_   4096
#define NQKV 1536
#define QKV_STRIDE 2097152   // B*H*L*DH
#define LOG2E 1.4426950408889634f

// Scratch (device globals; no allocations allowed).
// q (prescaled by 0.125*log2e), k: [B,H,L,Dh], dh-dim perm'd per 8-group.
// v: transposed per 64-row tile [B,H,L/64,Dh,64], key-dim perm'd per 8-group.
__device__ unsigned g_qkv[3 * QKV_STRIDE];
__device__ unsigned g_ao[M_ * D_];       // tf32 bits, e-dim perm'd
__device__ unsigned g_xt[M_ * D_];       // tf32 x, k-dim perm'd
__device__ unsigned g_w1[NQKV * D_];     // tf32 w_qkv, k-dim perm'd
__device__ unsigned g_w2[D_ * D_];       // tf32 w_out, k-dim perm'd

__device__ __forceinline__ unsigned f2tf(float x) {
    unsigned u; asm("cvt.rna.tf32.f32 %0, %1;" : "=r"(u) : "f"(x)); return u;
}
__device__ __forceinline__ float ex2(float x) {
    float r; asm("ex2.approx.f32 %0, %1;" : "=f"(r) : "f"(x)); return r;
}
__device__ __forceinline__ unsigned sptr(const void* p) {
    return (unsigned)__cvta_generic_to_shared(p);
}
#define CP16(d, s) asm volatile("cp.async.cg.shared.global [%0], [%1], 16;" :: "r"(d), "l"(s) : "memory")
#define CP8Z(d, s, sz) asm volatile("cp.async.ca.shared.global [%0], [%1], 8, %2;" :: "r"(d), "l"(s), "r"(sz) : "memory")
__device__ __forceinline__ void cp_commit() { asm volatile("cp.async.commit_group;" ::: "memory"); }
__device__ __forceinline__ void cp_wait0()  { asm volatile("cp.async.wait_group 0;" ::: "memory"); }
__device__ __forceinline__ void cp_wait1()  { asm volatile("cp.async.wait_group 1;" ::: "memory"); }

__device__ __forceinline__ void mma8(float* c,
                                     unsigned a0, unsigned a1, unsigned a2, unsigned a3,
                                     unsigned b0, unsigned b1) {
    asm volatile("mma.sync.aligned.m16n8k8.row.col.f32.tf32.tf32.f32 "
                 "{%0,%1,%2,%3}, {%4,%5,%6,%7}, {%8,%9}, {%0,%1,%2,%3};"
                 : "+f"(c[0]), "+f"(c[1]), "+f"(c[2]), "+f"(c[3])
                 : "r"(a0), "r"(a1), "r"(a2), "r"(a3), "r"(b0), "r"(b1));
}

// ---------------------------------------------------------------------------
// Prepass: fp32 -> tf32 (RNA) with per-8-group permutation [0,4,1,5,2,6,3,7].
// stored[p] holds orig[((p&1)<<2)|(p>>1)]; makes mma (t,t+4) pairs contiguous.
// ---------------------------------------------------------------------------
__global__ __launch_bounds__(256) void prep_tf32(const float* __restrict__ src,
                                                 unsigned* __restrict__ dst, int n8)
{
    int i = blockIdx.x * blockDim.x + threadIdx.x;
    if (i >= n8) return;
    const float4* s = (const float4*)(src + (size_t)i * 8);
    float4 lo = s[0], hi = s[1];
    uint4 o0, o1;
    o0.x = f2tf(lo.x); o0.y = f2tf(hi.x); o0.z = f2tf(lo.y); o0.w = f2tf(hi.y);
    o1.x = f2tf(lo.z); o1.y = f2tf(hi.z); o1.z = f2tf(lo.w); o1.w = f2tf(hi.w);
    uint4* d = (uint4*)(dst + (size_t)i * 8);
    d[0] = o0; d[1] = o1;
}

// ---------------------------------------------------------------------------
// tf32 GEMM, cp.async double-buffered, operands pre-converted+permuted.
// EPI=0: scatter qkv.  EPI=1: A := g_ao, write out + bias (fp32).
// ---------------------------------------------------------------------------
#define GP 40
#define GEMM_SMEM (2 * 2 * 128 * GP * 4)

template <int NTOT, int EPI>
__global__ __launch_bounds__(256, 2) void gemm_tf32(const unsigned* __restrict__ A,
                                                    const unsigned* __restrict__ Wt,
                                                    const float* __restrict__ bias,
                                                    float* __restrict__ out)
{
    extern __shared__ unsigned gsm[];
    unsigned* As = gsm;                 // [2][128][GP]
    unsigned* Bs = gsm + 2 * 128 * GP;  // [2][128][GP]

    const int m0 = blockIdx.y * 128;
    const int n0 = blockIdx.x * 128;
    const int tid  = threadIdx.x;
    const int warp = tid >> 5, lane = tid & 31;
    const int g = lane >> 2, t = lane & 3;
    const int wm = warp >> 1, wn = warp & 1;

    // EPI=1 reads the attention output scratch (fix for R5 nullptr bug)
    const unsigned* Ap = (EPI == 1) ? (const unsigned*)g_ao : A;

    float C[2][8][4] = {};

    auto issue = [&](int ki, int buf) {
        int k0 = ki * 32;
        unsigned* Ad = As + buf * 128 * GP;
        unsigned* Bd = Bs + buf * 128 * GP;
        #pragma unroll
        for (int p = 0; p < 4; p++) {
            int c = tid + p * 256;
            int r = c >> 3, col = (c & 7) * 4;
            CP16(sptr(&Ad[r * GP + col]), &Ap[(size_t)(m0 + r) * D_ + k0 + col]);
            CP16(sptr(&Bd[r * GP + col]), &Wt[(size_t)(n0 + r) * D_ + k0 + col]);
        }
    };

    issue(0, 0);
    cp_commit();

    for (int ki = 0; ki < 16; ki++) {
        int buf = ki & 1;
        __syncthreads();
        if (ki + 1 < 16) { issue(ki + 1, buf ^ 1); cp_commit(); cp_wait1(); }
        else             { cp_wait0(); }
        __syncthreads();

        const unsigned* Af = As + buf * 128 * GP;
        const unsigned* Bf = Bs + buf * 128 * GP;
        #pragma unroll
        for (int kk = 0; kk < 32; kk += 8) {
            unsigned a[2][4];
            #pragma unroll
            for (int mf = 0; mf < 2; mf++) {
                int rb = wm * 32 + mf * 16;
                uint2 u0 = *(const uint2*)&Af[(rb + g    ) * GP + kk + 2 * t];
                uint2 u1 = *(const uint2*)&Af[(rb + g + 8) * GP + kk + 2 * t];
                a[mf][0] = u0.x; a[mf][1] = u1.x; a[mf][2] = u0.y; a[mf][3] = u1.y;
            }
            #pragma unroll
            for (int nf = 0; nf < 8; nf++) {
                int nb = wn * 64 + nf * 8;
                uint2 bv = *(const uint2*)&Bf[(nb + g) * GP + kk + 2 * t];
                mma8(C[0][nf], a[0][0], a[0][1], a[0][2], a[0][3], bv.x, bv.y);
                mma8(C[1][nf], a[1][0], a[1][1], a[1][2], a[1][3], bv.x, bv.y);
            }
        }
    }

    const int pp0 = ((2 * t & 3) << 1) | (t >> 1);
    const int pp1 = (((2 * t + 1) & 3) << 1) | (t >> 1);
    const int pg  = ((g & 3) << 1) | (g >> 2);
    const float qscale = 0.125f * LOG2E;

    if (EPI == 0) {
        #pragma unroll
        for (int mf = 0; mf < 2; mf++) {
            int m = m0 + wm * 32 + mf * 16;
            #pragma unroll
            for (int nf = 0; nf < 8; nf++) {
                int n   = n0 + wn * 64 + nf * 8 + 2 * t;
                int sec = n >> 9;
                int h   = (n >> 6) & 7;
                int dh  = n & 63;
                int dhb = dh & ~7;
                #pragma unroll
                for (int rr = 0; rr < 2; rr++) {
                    int mm = m + g + rr * 8;
                    int b  = mm >> 11;
                    int l  = mm & 2047;
                    float c0v = C[mf][nf][rr * 2 + 0];
                    float c1v = C[mf][nf][rr * 2 + 1];
                    if (sec == 0) { c0v *= qscale; c1v *= qscale; }
                    unsigned v0 = f2tf(c0v), v1 = f2tf(c1v);
                    if (sec < 2) {
                        unsigned* dst = g_qkv + (size_t)sec * QKV_STRIDE
                                      + (size_t)(((b * H_ + h) * L_ + l) * DH_) + dhb;
                        dst[pp0] = v0; dst[pp1] = v1;
                    } else {
                        int keyp = ((l >> 3) & 7) * 8 + pg;   // key within tile, perm'd
                        unsigned* vb2 = g_qkv + 2 * (size_t)QKV_STRIDE
                                      + (size_t)(b * H_ + h) * L_ * DH_
                                      + (l >> 6) * 4096 + keyp;
                        vb2[(size_t)dh * 64]       = v0;
                        vb2[(size_t)(dh + 1) * 64] = v1;
                    }
                }
            }
        }
    } else {
        #pragma unroll
        for (int mf = 0; mf < 2; mf++) {
            int m = m0 + wm * 32 + mf * 16;
            #pragma unroll
            for (int nf = 0; nf < 8; nf++) {
                int n = n0 + wn * 64 + nf * 8 + 2 * t;
                float b0v = bias[n], b1v = bias[n + 1];
                #pragma unroll
                for (int rr = 0; rr < 2; rr++) {
                    int mm = m + g + rr * 8;
                    float2 v;
                    v.x = C[mf][nf][rr * 2 + 0] + b0v;
                    v.y = C[mf][nf][rr * 2 + 1] + b1v;
                    *(float2*)&out[(size_t)mm * NTOT + n] = v;
                }
            }
        }
    }
}

// ---------------------------------------------------------------------------
// Flash attention, tf32 mma, base-2 softmax, bias fast paths.
// ---------------------------------------------------------------------------
#define KP 72
#define ATTN_SMEM ((4 * 64 * KP + 128 * KP) * 4 + 128 * 8 + 2 * 64 * 8)

__global__ __launch_bounds__(256, 2) void attn_tf32(const float* __restrict__ pos,
                                                    const float* __restrict__ log_sigma,
                                                    const float* __restrict__ gbias_p,
                                                    const int*   __restrict__ nsp)
{
    extern __shared__ unsigned smA[];
    unsigned* Ks = smA;                   // [2][64][KP]
    unsigned* Vs = smA + 2 * 64 * KP;     // [2][64][KP]  (V^T tiles)
    unsigned* Ps = smA + 4 * 64 * KP;     // [128][KP]  (Q staging, then P)
    float2* qpos = (float2*)(Ps + 128 * KP);
    float2* kpos = qpos + 128;

    const int i0 = blockIdx.x * 128;
    const int bh = blockIdx.y;
    const int b  = bh >> 3, h = bh & 7;
    const int Ls = *nsp;
    const float gb2 = (*gbias_p) * LOG2E;
    const float c2  = 0.5f * __expf(-2.0f * log_sigma[h]) * LOG2E;
    const float nc2 = -c2;

    const int tid  = threadIdx.x;
    const int warp = tid >> 5, lane = tid & 31;
    const int g = lane >> 2, t = lane & 3;
    const int wr = warp * 16;
    const int pp0 = ((2 * t & 3) << 1) | (t >> 1);
    const int pp1 = (((2 * t + 1) & 3) << 1) | (t >> 1);

    const unsigned* qb = g_qkv + 0 * (size_t)QKV_STRIDE + (size_t)(b * H_ + h) * L_ * DH_;
    const unsigned* kb = g_qkv + 1 * (size_t)QKV_STRIDE + (size_t)(b * H_ + h) * L_ * DH_;
    const unsigned* vb = g_qkv + 2 * (size_t)QKV_STRIDE + (size_t)(b * H_ + h) * L_ * DH_;

    // Stage Q tile (128x64) into Ps
    #pragma unroll
    for (int p = 0; p < 8; p++) {
        int c = tid + p * 256;
        int r = c >> 4, c4 = (c & 15) * 4;
        *(uint4*)&Ps[r * KP + c4] = *(const uint4*)&qb[(size_t)(i0 + r) * DH_ + c4];
    }
    if (tid < 128) {
        int iG = i0 + tid;
        float2 v = make_float2(0.f, 0.f);
        if (iG < Ls) v = *(const float2*)&pos[(size_t)(b * Ls + iG) * 2];
        qpos[tid] = v;
    }
    __syncthreads();

    unsigned qf[8][4];
    #pragma unroll
    for (int kf = 0; kf < 8; kf++) {
        uint2 u0 = *(const uint2*)&Ps[(wr + g    ) * KP + kf * 8 + 2 * t];
        uint2 u1 = *(const uint2*)&Ps[(wr + g + 8) * KP + kf * 8 + 2 * t];
        qf[kf][0] = u0.x; qf[kf][1] = u1.x; qf[kf][2] = u0.y; qf[kf][3] = u1.y;
    }

    float qx0, qy0, qx1, qy1; bool iin0, iin1;
    {
        int r0 = i0 + wr + g;
        float2 p0 = qpos[wr + g], p1 = qpos[wr + g + 8];
        qx0 = p0.x; qy0 = p0.y; qx1 = p1.x; qy1 = p1.y;
        iin0 = r0 < Ls; iin1 = (r0 + 8) < Ls;
    }

    auto issue = [&](int jt, int buf) {
        const unsigned* kt = kb + (size_t)jt * 64 * 64;
        const unsigned* vt = vb + (size_t)jt * 4096;
        unsigned* Kd = Ks + buf * 64 * KP;
        unsigned* Vd = Vs + buf * 64 * KP;
        #pragma unroll
        for (int p = 0; p < 4; p++) {
            int c = tid + p * 256;
            int r = c >> 4, c4 = (c & 15) * 4;
            CP16(sptr(&Kd[r * KP + c4]), kt + r * 64 + c4);
            CP16(sptr(&Vd[r * KP + c4]), vt + r * 64 + c4);
        }
        if (tid < 64) {
            int jG = jt * 64 + tid;
            CP8Z(sptr(&kpos[buf * 64 + tid]), &pos[(size_t)(b * Ls + jG) * 2],
                 (jG < Ls) ? 8u : 0u);
        }
    };

    float O[8][4] = {};
    float m0 = -1e30f, m1 = -1e30f, l0 = 0.f, l1 = 0.f;
    const bool i_allsp = (i0 + 128) <= Ls;
    const bool i_allout = i0 >= Ls;

    issue(0, 0);
    cp_commit();

    for (int jt = 0; jt < 32; jt++) {
        int buf = jt & 1;
        __syncthreads();
        if (jt + 1 < 32) { issue(jt + 1, buf ^ 1); cp_commit(); cp_wait1(); }
        else             { cp_wait0(); }
        __syncthreads();

        const unsigned* Kf = Ks + buf * 64 * KP;
        const unsigned* Vf = Vs + buf * 64 * KP;
        const float2*   kp = kpos + buf * 64;
        const int j0 = jt * 64;

        // S = Q K^T
        float S[8][4] = {};
        #pragma unroll
        for (int nf = 0; nf < 8; nf++) {
            #pragma unroll
            for (int kf = 0; kf < 8; kf++) {
                uint2 bv = *(const uint2*)&Kf[(nf * 8 + g) * KP + kf * 8 + 2 * t];
                mma8(S[nf], qf[kf][0], qf[kf][1], qf[kf][2], qf[kf][3], bv.x, bv.y);
            }
        }

        // Bias (3 paths) — S already includes scale*log2e via prescaled q
        if (i_allsp && (j0 + 64) <= Ls) {
            #pragma unroll
            for (int nf = 0; nf < 8; nf++) {
                int c0 = nf * 8 + 2 * t;
                float2 kp0 = kp[c0], kp1 = kp[c0 + 1];
                float dx, dy, dd;
                dx = qx0 - kp0.x; dy = qy0 - kp0.y; dd = fmaf(dy, dy, dx * dx);
                S[nf][0] = fmaf(dd, nc2, S[nf][0]);
                dx = qx0 - kp1.x; dy = qy0 - kp1.y; dd = fmaf(dy, dy, dx * dx);
                S[nf][1] = fmaf(dd, nc2, S[nf][1]);
                dx = qx1 - kp0.x; dy = qy1 - kp0.y; dd = fmaf(dy, dy, dx * dx);
                S[nf][2] = fmaf(dd, nc2, S[nf][2]);
                dx = qx1 - kp1.x; dy = qy1 - kp1.y; dd = fmaf(dy, dy, dx * dx);
                S[nf][3] = fmaf(dd, nc2, S[nf][3]);
            }
        } else if (j0 >= Ls || i_allout) {
            #pragma unroll
            for (int nf = 0; nf < 8; nf++) {
                S[nf][0] += gb2; S[nf][1] += gb2; S[nf][2] += gb2; S[nf][3] += gb2;
            }
        } else {
            #pragma unroll
            for (int nf = 0; nf < 8; nf++) {
                int c0 = nf * 8 + 2 * t;
                int jg0 = j0 + c0;
                float2 kp0 = kp[c0], kp1 = kp[c0 + 1];
                bool jin0 = jg0 < Ls, jin1 = (jg0 + 1) < Ls;
                float dx, dy, dd;
                dx = qx0 - kp0.x; dy = qy0 - kp0.y; dd = fmaf(dy, dy, dx * dx);
                S[nf][0] += (iin0 && jin0) ? dd * nc2 : gb2;
                dx = qx0 - kp1.x; dy = qy0 - kp1.y; dd = fmaf(dy, dy, dx * dx);
                S[nf][1] += (iin0 && jin1) ? dd * nc2 : gb2;
                dx = qx1 - kp0.x; dy = qy1 - kp0.y; dd = fmaf(dy, dy, dx * dx);
                S[nf][2] += (iin1 && jin0) ? dd * nc2 : gb2;
                dx = qx1 - kp1.x; dy = qy1 - kp1.y; dd = fmaf(dy, dy, dx * dx);
                S[nf][3] += (iin1 && jin1) ? dd * nc2 : gb2;
            }
        }

        // Online softmax (base 2)
        float mx0 = -1e30f, mx1 = -1e30f;
        #pragma unroll
        for (int nf = 0; nf < 8; nf++) {
            mx0 = fmaxf(mx0, fmaxf(S[nf][0], S[nf][1]));
            mx1 = fmaxf(mx1, fmaxf(S[nf][2], S[nf][3]));
        }
        mx0 = fmaxf(mx0, __shfl_xor_sync(0xffffffffu, mx0, 1));
        mx0 = fmaxf(mx0, __shfl_xor_sync(0xffffffffu, mx0, 2));
        mx1 = fmaxf(mx1, __shfl_xor_sync(0xffffffffu, mx1, 1));
        mx1 = fmaxf(mx1, __shfl_xor_sync(0xffffffffu, mx1, 2));
        float mn0 = fmaxf(m0, mx0), mn1 = fmaxf(m1, mx1);
        float a0 = ex2(m0 - mn0), a1 = ex2(m1 - mn1);
        m0 = mn0; m1 = mn1;
        float s0 = 0.f, s1 = 0.f;
        #pragma unroll
        for (int nf = 0; nf < 8; nf++) {
            S[nf][0] = ex2(S[nf][0] - m0);
            S[nf][1] = ex2(S[nf][1] - m0);
            S[nf][2] = ex2(S[nf][2] - m1);
            S[nf][3] = ex2(S[nf][3] - m1);
            s0 += S[nf][0] + S[nf][1];
            s1 += S[nf][2] + S[nf][3];
        }
        s0 += __shfl_xor_sync(0xffffffffu, s0, 1);
        s0 += __shfl_xor_sync(0xffffffffu, s0, 2);
        s1 += __shfl_xor_sync(0xffffffffu, s1, 1);
        s1 += __shfl_xor_sync(0xffffffffu, s1, 2);
        l0 = l0 * a0 + s0; l1 = l1 * a1 + s1;
        #pragma unroll
        for (int df = 0; df < 8; df++) {
            O[df][0] *= a0; O[df][1] *= a0; O[df][2] *= a1; O[df][3] *= a1;
        }

        // P -> warp-private smem (tf32, key-perm'd), reload as A fragments
        __syncwarp();
        #pragma unroll
        for (int nf = 0; nf < 8; nf++) {
            int cb = nf * 8;
            Ps[(wr + g    ) * KP + cb + pp0] = f2tf(S[nf][0]);
            Ps[(wr + g    ) * KP + cb + pp1] = f2tf(S[nf][1]);
            Ps[(wr + g + 8) * KP + cb + pp0] = f2tf(S[nf][2]);
            Ps[(wr + g + 8) * KP + cb + pp1] = f2tf(S[nf][3]);
        }
        __syncwarp();

        // O += P V   (V^T tile: rows = dh, cols = key perm'd)
        #pragma unroll
        for (int kf = 0; kf < 8; kf++) {
            uint2 u0 = *(const uint2*)&Ps[(wr + g    ) * KP + kf * 8 + 2 * t];
            uint2 u1 = *(const uint2*)&Ps[(wr + g + 8) * KP + kf * 8 + 2 * t];
            #pragma unroll
            for (int df = 0; df < 8; df++) {
                uint2 bv = *(const uint2*)&Vf[(df * 8 + g) * KP + kf * 8 + 2 * t];
                mma8(O[df], u0.x, u1.x, u0.y, u1.y, bv.x, bv.y);
            }
        }
    }

    // Normalize and write g_ao as tf32, e-dim perm'd for outproj
    float il0 = 1.f / l0, il1 = 1.f / l1;
    int r0 = i0 + wr + g, r1 = r0 + 8;
    #pragma unroll
    for (int df = 0; df < 8; df++) {
        int dhb = df * 8;
        unsigned* o0p = &g_ao[(size_t)(b * L_ + r0) * D_ + h * DH_ + dhb];
        unsigned* o1p = &g_ao[(size_t)(b * L_ + r1) * D_ + h * DH_ + dhb];
        o0p[pp0] = f2tf(O[df][0] * il0);
        o0p[pp1] = f2tf(O[df][1] * il0);
        o1p[pp0] = f2tf(O[df][2] * il1);
        o1p[pp1] = f2tf(O[df][3] * il1);
    }
}

// ---------------------------------------------------------------------------
extern "C" void kernel_launch(void* const* d_in, const int* in_sizes, int n_in,
                              void* d_out, int out_size)
{
    const float* x     = (const float*)d_in[0];
    const float* pos   = (const float*)d_in[1];
    const float* wqkv  = (const float*)d_in[2];
    const float* wout  = (const float*)d_in[3];
    const float* bout  = (const float*)d_in[4];
    const float* lsig  = (const float*)d_in[5];
    const float* gbias = (const float*)d_in[6];
    const int*   nsp   = (const int*)d_in[7];
    float* out = (float*)d_out;

    unsigned *p_xt, *p_w1, *p_w2;
    cudaGetSymbolAddress((void**)&p_xt, g_xt);
    cudaGetSymbolAddress((void**)&p_w1, g_w1);
    cudaGetSymbolAddress((void**)&p_w2, g_w2);

    cudaFuncSetAttribute(attn_tf32, cudaFuncAttributeMaxDynamicSharedMemorySize, ATTN_SMEM);
    cudaFuncSetAttribute(gemm_tf32<NQKV, 0>, cudaFuncAttributeMaxDynamicSharedMemorySize, GEMM_SMEM);
    cudaFuncSetAttribute(gemm_tf32<D_, 1>, cudaFuncAttributeMaxDynamicSharedMemorySize, GEMM_SMEM);

    prep_tf32<<<(M_ * D_ / 8 + 255) / 256, 256>>>(x, p_xt, M_ * D_ / 8);
    prep_tf32<<<(NQKV * D_ / 8 + 255) / 256, 256>>>(wqkv, p_w1, NQKV * D_ / 8);
    prep_tf32<<<(D_ * D_ / 8 + 255) / 256, 256>>>(wout, p_w2, D_ * D_ / 8);

    gemm_tf32<NQKV, 0><<<dim3(NQKV / 128, M_ / 128), 256, GEMM_SMEM>>>(p_xt, p_w1, nullptr, nullptr);
    attn_tf32<<<dim3(L_ / 128, B_ * H_), 256, ATTN_SMEM>>>(pos, lsig, gbias, nsp);
    gemm_tf32<D_, 1><<<dim3(D_ / 128, M_ / 128), 256, GEMM_SMEM>>>(nullptr, p_w2, bout, out);
}

// round 8
// speedup vs baseline: 6.1452x; 1.6842x over previous
#include <cuda_runtime.h>
#include <cuda_fp16.h>

#define B_   2
#define H_   8
#define L_   2048
#define DH_  64
#define D_   512
#define M_   4096
#define NQKV 1536
#define D2   256                 // uints (half2) per row of a D_-wide matrix
#define QS_U 1048576             // uints per qkv section: B*H*L*DH/2
#define LOG2E 1.4426950408889634f

// Scratch (device globals; no allocations allowed). All tensor data as half2
// (stored in unsigned), contraction dim permuted per 8-pair group so that the
// m16n8k16 fragment pairs (t, t+4) sit at stored slots (2t, 2t+1).
// q (prescaled by 0.125*log2e), k: [B,H,L,DH/2 uints]
// v: transposed per 64-key tile [B,H,L/64, DH rows, 32 uints(keys perm'd)]
__device__ unsigned g_qkv[3 * QS_U];
__device__ unsigned g_ao[M_ * D2];       // attn out, e-dim perm'd
__device__ unsigned g_xt[M_ * D2];       // x,      k-dim perm'd
__device__ unsigned g_w1[NQKV * D2];     // w_qkv,  k-dim perm'd
__device__ unsigned g_w2[D_ * D2];       // w_out,  k-dim perm'd

__device__ __forceinline__ unsigned pk2(float a, float b) {
    __half2 h = __floats2half2_rn(a, b);       // low = a
    return *(unsigned*)&h;
}
__device__ __forceinline__ float ex2(float x) {
    float r; asm("ex2.approx.f32 %0, %1;" : "=f"(r) : "f"(x)); return r;
}
__device__ __forceinline__ unsigned sptr(const void* p) {
    return (unsigned)__cvta_generic_to_shared(p);
}
#define CP16(d, s) asm volatile("cp.async.cg.shared.global [%0], [%1], 16;" :: "r"(d), "l"(s) : "memory")
#define CP8Z(d, s, sz) asm volatile("cp.async.ca.shared.global [%0], [%1], 8, %2;" :: "r"(d), "l"(s), "r"(sz) : "memory")
__device__ __forceinline__ void cp_commit() { asm volatile("cp.async.commit_group;" ::: "memory"); }
__device__ __forceinline__ void cp_wait0()  { asm volatile("cp.async.wait_group 0;" ::: "memory"); }
__device__ __forceinline__ void cp_wait1()  { asm volatile("cp.async.wait_group 1;" ::: "memory"); }

__device__ __forceinline__ void mma16(float* c,
                                      unsigned a0, unsigned a1, unsigned a2, unsigned a3,
                                      unsigned b0, unsigned b1) {
    asm volatile("mma.sync.aligned.m16n8k16.row.col.f32.f16.f16.f32 "
                 "{%0,%1,%2,%3}, {%4,%5,%6,%7}, {%8,%9}, {%0,%1,%2,%3};"
                 : "+f"(c[0]), "+f"(c[1]), "+f"(c[2]), "+f"(c[3])
                 : "r"(a0), "r"(a1), "r"(a2), "r"(a3), "r"(b0), "r"(b1));
}

// ---------------------------------------------------------------------------
// Prepass: fp32 -> half2 with per-8-pair permutation [0,4,1,5,2,6,3,7].
// Each thread handles 16 floats -> 8 permuted half2 uints.
// ---------------------------------------------------------------------------
__global__ __launch_bounds__(256) void prep_h(const float* __restrict__ src,
                                              unsigned* __restrict__ dst, int n16)
{
    int i = blockIdx.x * blockDim.x + threadIdx.x;
    if (i >= n16) return;
    const float4* s = (const float4*)(src + (size_t)i * 16);
    float4 s0 = s[0], s1 = s[1], s2 = s[2], s3 = s[3];
    uint4 o0, o1;
    o0.x = pk2(s0.x, s0.y); o0.y = pk2(s2.x, s2.y);
    o0.z = pk2(s0.z, s0.w); o0.w = pk2(s2.z, s2.w);
    o1.x = pk2(s1.x, s1.y); o1.y = pk2(s3.x, s3.y);
    o1.z = pk2(s1.z, s1.w); o1.w = pk2(s3.z, s3.w);
    uint4* d = (uint4*)(dst + (size_t)i * 8);
    d[0] = o0; d[1] = o1;
}

// ---------------------------------------------------------------------------
// fp16 GEMM, cp.async double-buffered. k-chunk = 32 uints (64 halves).
// EPI=0: scatter qkv.  EPI=1: A := g_ao, write out + bias (fp32).
// ---------------------------------------------------------------------------
#define GP 40
#define GEMM_SMEM (2 * 2 * 128 * GP * 4)

template <int NTOT, int EPI>
__global__ __launch_bounds__(256, 2) void gemm_h(const unsigned* __restrict__ A,
                                                 const unsigned* __restrict__ Wt,
                                                 const float* __restrict__ bias,
                                                 float* __restrict__ out)
{
    extern __shared__ unsigned gsm[];
    unsigned* As = gsm;                 // [2][128][GP]
    unsigned* Bs = gsm + 2 * 128 * GP;  // [2][128][GP]

    const int m0 = blockIdx.y * 128;
    const int n0 = blockIdx.x * 128;
    const int tid  = threadIdx.x;
    const int warp = tid >> 5, lane = tid & 31;
    const int g = lane >> 2, t = lane & 3;
    const int wm = warp >> 1, wn = warp & 1;

    const unsigned* Ap = (EPI == 1) ? (const unsigned*)g_ao : A;

    float C[2][8][4] = {};

    auto issue = [&](int ki, int buf) {
        int k0 = ki * 32;                       // uints
        unsigned* Ad = As + buf * 128 * GP;
        unsigned* Bd = Bs + buf * 128 * GP;
        #pragma unroll
        for (int p = 0; p < 4; p++) {
            int c = tid + p * 256;
            int r = c >> 3, col = (c & 7) * 4;
            CP16(sptr(&Ad[r * GP + col]), &Ap[(size_t)(m0 + r) * D2 + k0 + col]);
            CP16(sptr(&Bd[r * GP + col]), &Wt[(size_t)(n0 + r) * D2 + k0 + col]);
        }
    };

    issue(0, 0);
    cp_commit();

    for (int ki = 0; ki < 8; ki++) {
        int buf = ki & 1;
        __syncthreads();
        if (ki + 1 < 8) { issue(ki + 1, buf ^ 1); cp_commit(); cp_wait1(); }
        else            { cp_wait0(); }
        __syncthreads();

        const unsigned* Af = As + buf * 128 * GP;
        const unsigned* Bf = Bs + buf * 128 * GP;
        #pragma unroll
        for (int kk = 0; kk < 32; kk += 8) {    // 4 k16 steps
            unsigned a[2][4];
            #pragma unroll
            for (int mf = 0; mf < 2; mf++) {
                int rb = wm * 32 + mf * 16;
                uint2 u0 = *(const uint2*)&Af[(rb + g    ) * GP + kk + 2 * t];
                uint2 u1 = *(const uint2*)&Af[(rb + g + 8) * GP + kk + 2 * t];
                a[mf][0] = u0.x; a[mf][1] = u1.x; a[mf][2] = u0.y; a[mf][3] = u1.y;
            }
            #pragma unroll
            for (int nf = 0; nf < 8; nf++) {
                int nb = wn * 64 + nf * 8;
                uint2 bv = *(const uint2*)&Bf[(nb + g) * GP + kk + 2 * t];
                mma16(C[0][nf], a[0][0], a[0][1], a[0][2], a[0][3], bv.x, bv.y);
                mma16(C[1][nf], a[1][0], a[1][1], a[1][2], a[1][3], bv.x, bv.y);
            }
        }
    }

    const float qscale = 0.125f * LOG2E;

    if (EPI == 0) {
        __half* hv = (__half*)g_qkv;
        #pragma unroll
        for (int mf = 0; mf < 2; mf++) {
            int m = m0 + wm * 32 + mf * 16;
            #pragma unroll
            for (int nf = 0; nf < 8; nf++) {
                int n   = n0 + wn * 64 + nf * 8 + 2 * t;
                int sec = n >> 9;
                int h   = (n >> 6) & 7;
                int dh  = n & 63;
                // permuted uint column for q/k (contraction dim = dh)
                int jp = dh >> 1;
                int jj = jp & 7;
                int col = (jp >> 3) * 8 + (((jj & 3) << 1) | (jj >> 2));
                #pragma unroll
                for (int rr = 0; rr < 2; rr++) {
                    int mm = m + g + rr * 8;
                    int b  = mm >> 11;
                    int l  = mm & 2047;
                    float c0v = C[mf][nf][rr * 2 + 0];
                    float c1v = C[mf][nf][rr * 2 + 1];
                    if (sec == 0) { c0v *= qscale; c1v *= qscale; }
                    if (sec < 2) {
                        g_qkv[(size_t)sec * QS_U
                              + (size_t)((b * H_ + h) * L_ + l) * 32 + col] = pk2(c0v, c1v);
                    } else {
                        // V^T: keys permuted; store two single halves (rows dh, dh+1)
                        int kp = (l & 63) >> 1;
                        int j2 = kp & 7;
                        int ks = ((j2 & 3) << 1) | (j2 >> 2);
                        int khalf = ((kp >> 3) * 8 + ks) * 2 + (l & 1);
                        size_t vb2 = (size_t)2 * QS_U * 2
                                   + (size_t)(b * H_ + h) * L_ * DH_
                                   + (size_t)(l >> 6) * 4096 + khalf;
                        hv[vb2 + (size_t)dh * 64]       = __float2half_rn(c0v);
                        hv[vb2 + (size_t)(dh + 1) * 64] = __float2half_rn(c1v);
                    }
                }
            }
        }
    } else {
        #pragma unroll
        for (int mf = 0; mf < 2; mf++) {
            int m = m0 + wm * 32 + mf * 16;
            #pragma unroll
            for (int nf = 0; nf < 8; nf++) {
                int n = n0 + wn * 64 + nf * 8 + 2 * t;
                float b0v = bias[n], b1v = bias[n + 1];
                #pragma unroll
                for (int rr = 0; rr < 2; rr++) {
                    int mm = m + g + rr * 8;
                    float2 v;
                    v.x = C[mf][nf][rr * 2 + 0] + b0v;
                    v.y = C[mf][nf][rr * 2 + 1] + b1v;
                    *(float2*)&out[(size_t)mm * NTOT + n] = v;
                }
            }
        }
    }
}

// ---------------------------------------------------------------------------
// Flash attention, fp16 mma, base-2 softmax, bias fast paths.
// ---------------------------------------------------------------------------
#define KP 40
#define ATTN_SMEM ((4 * 64 * KP + 128 * KP) * 4 + 128 * 8 + 2 * 64 * 8)

__global__ __launch_bounds__(256, 2) void attn_h(const float* __restrict__ pos,
                                                 const float* __restrict__ log_sigma,
                                                 const float* __restrict__ gbias_p,
                                                 const int*   __restrict__ nsp)
{
    extern __shared__ unsigned smA[];
    unsigned* Ks = smA;                   // [2][64][KP]
    unsigned* Vs = smA + 2 * 64 * KP;     // [2][64][KP]  (V^T tiles)
    unsigned* Ps = smA + 4 * 64 * KP;     // [128][KP]  (Q staging, then P)
    float2* qpos = (float2*)(Ps + 128 * KP);
    float2* kpos = qpos + 128;

    const int i0 = blockIdx.x * 128;
    const int bh = blockIdx.y;
    const int b  = bh >> 3, h = bh & 7;
    const int Ls = *nsp;
    const float gb2 = (*gbias_p) * LOG2E;
    const float nc2 = -0.5f * __expf(-2.0f * log_sigma[h]) * LOG2E;

    const int tid  = threadIdx.x;
    const int warp = tid >> 5, lane = tid & 31;
    const int g = lane >> 2, t = lane & 3;
    const int wr = warp * 16;

    const unsigned* qb = g_qkv + (size_t)(b * H_ + h) * L_ * 32;
    const unsigned* kb = g_qkv + (size_t)QS_U + (size_t)(b * H_ + h) * L_ * 32;
    const unsigned* vb = g_qkv + 2 * (size_t)QS_U + (size_t)(b * H_ + h) * L_ * 32;

    // Stage Q tile (128 rows x 32 uints) into Ps
    #pragma unroll
    for (int p = 0; p < 4; p++) {
        int c = tid + p * 256;
        int r = c >> 3, c4 = (c & 7) * 4;
        *(uint4*)&Ps[r * KP + c4] = *(const uint4*)&qb[(size_t)(i0 + r) * 32 + c4];
    }
    if (tid < 128) {
        int iG = i0 + tid;
        float2 v = make_float2(0.f, 0.f);
        if (iG < Ls) v = *(const float2*)&pos[(size_t)(b * Ls + iG) * 2];
        qpos[tid] = v;
    }
    __syncthreads();

    unsigned qf[4][4];
    #pragma unroll
    for (int kf = 0; kf < 4; kf++) {
        uint2 u0 = *(const uint2*)&Ps[(wr + g    ) * KP + kf * 8 + 2 * t];
        uint2 u1 = *(const uint2*)&Ps[(wr + g + 8) * KP + kf * 8 + 2 * t];
        qf[kf][0] = u0.x; qf[kf][1] = u1.x; qf[kf][2] = u0.y; qf[kf][3] = u1.y;
    }

    float qx0, qy0, qx1, qy1; bool iin0, iin1;
    {
        int r0 = i0 + wr + g;
        float2 p0 = qpos[wr + g], p1 = qpos[wr + g + 8];
        qx0 = p0.x; qy0 = p0.y; qx1 = p1.x; qy1 = p1.y;
        iin0 = r0 < Ls; iin1 = (r0 + 8) < Ls;
    }

    auto issue = [&](int jt, int buf) {
        const unsigned* kt = kb + (size_t)jt * 2048;   // 64 rows x 32 uints
        const unsigned* vt = vb + (size_t)jt * 2048;
        unsigned* Kd = Ks + buf * 64 * KP;
        unsigned* Vd = Vs + buf * 64 * KP;
        #pragma unroll
        for (int p = 0; p < 2; p++) {
            int c = tid + p * 256;
            int r = c >> 3, c4 = (c & 7) * 4;
            CP16(sptr(&Kd[r * KP + c4]), kt + r * 32 + c4);
            CP16(sptr(&Vd[r * KP + c4]), vt + r * 32 + c4);
        }
        if (tid < 64) {
            int jG = jt * 64 + tid;
            CP8Z(sptr(&kpos[buf * 64 + tid]), &pos[(size_t)(b * Ls + jG) * 2],
                 (jG < Ls) ? 8u : 0u);
        }
    };

    float O[8][4] = {};
    float m0 = -1e30f, m1 = -1e30f, l0 = 0.f, l1 = 0.f;
    const bool i_allsp = (i0 + 128) <= Ls;
    const bool i_allout = i0 >= Ls;

    issue(0, 0);
    cp_commit();

    for (int jt = 0; jt < 32; jt++) {
        int buf = jt & 1;
        __syncthreads();
        if (jt + 1 < 32) { issue(jt + 1, buf ^ 1); cp_commit(); cp_wait1(); }
        else             { cp_wait0(); }
        __syncthreads();

        const unsigned* Kf = Ks + buf * 64 * KP;
        const unsigned* Vf = Vs + buf * 64 * KP;
        const float2*   kp = kpos + buf * 64;
        const int j0 = jt * 64;

        // S = Q K^T  (4 k16 steps x 8 nf)
        float S[8][4] = {};
        #pragma unroll
        for (int nf = 0; nf < 8; nf++) {
            #pragma unroll
            for (int kf = 0; kf < 4; kf++) {
                uint2 bv = *(const uint2*)&Kf[(nf * 8 + g) * KP + kf * 8 + 2 * t];
                mma16(S[nf], qf[kf][0], qf[kf][1], qf[kf][2], qf[kf][3], bv.x, bv.y);
            }
        }

        // Bias (3 paths) — S already includes scale*log2e via prescaled q
        if (i_allsp && (j0 + 64) <= Ls) {
            #pragma unroll
            for (int nf = 0; nf < 8; nf++) {
                int c0 = nf * 8 + 2 * t;
                float2 kp0 = kp[c0], kp1 = kp[c0 + 1];
                float dx, dy, dd;
                dx = qx0 - kp0.x; dy = qy0 - kp0.y; dd = fmaf(dy, dy, dx * dx);
                S[nf][0] = fmaf(dd, nc2, S[nf][0]);
                dx = qx0 - kp1.x; dy = qy0 - kp1.y; dd = fmaf(dy, dy, dx * dx);
                S[nf][1] = fmaf(dd, nc2, S[nf][1]);
                dx = qx1 - kp0.x; dy = qy1 - kp0.y; dd = fmaf(dy, dy, dx * dx);
                S[nf][2] = fmaf(dd, nc2, S[nf][2]);
                dx = qx1 - kp1.x; dy = qy1 - kp1.y; dd = fmaf(dy, dy, dx * dx);
                S[nf][3] = fmaf(dd, nc2, S[nf][3]);
            }
        } else if (j0 >= Ls || i_allout) {
            #pragma unroll
            for (int nf = 0; nf < 8; nf++) {
                S[nf][0] += gb2; S[nf][1] += gb2; S[nf][2] += gb2; S[nf][3] += gb2;
            }
        } else {
            #pragma unroll
            for (int nf = 0; nf < 8; nf++) {
                int c0 = nf * 8 + 2 * t;
                int jg0 = j0 + c0;
                float2 kp0 = kp[c0], kp1 = kp[c0 + 1];
                bool jin0 = jg0 < Ls, jin1 = (jg0 + 1) < Ls;
                float dx, dy, dd;
                dx = qx0 - kp0.x; dy = qy0 - kp0.y; dd = fmaf(dy, dy, dx * dx);
                S[nf][0] += (iin0 && jin0) ? dd * nc2 : gb2;
                dx = qx0 - kp1.x; dy = qy0 - kp1.y; dd = fmaf(dy, dy, dx * dx);
                S[nf][1] += (iin0 && jin1) ? dd * nc2 : gb2;
                dx = qx1 - kp0.x; dy = qy1 - kp0.y; dd = fmaf(dy, dy, dx * dx);
                S[nf][2] += (iin1 && jin0) ? dd * nc2 : gb2;
                dx = qx1 - kp1.x; dy = qy1 - kp1.y; dd = fmaf(dy, dy, dx * dx);
                S[nf][3] += (iin1 && jin1) ? dd * nc2 : gb2;
            }
        }

        // Online softmax (base 2)
        float mx0 = -1e30f, mx1 = -1e30f;
        #pragma unroll
        for (int nf = 0; nf < 8; nf++) {
            mx0 = fmaxf(mx0, fmaxf(S[nf][0], S[nf][1]));
            mx1 = fmaxf(mx1, fmaxf(S[nf][2], S[nf][3]));
        }
        mx0 = fmaxf(mx0, __shfl_xor_sync(0xffffffffu, mx0, 1));
        mx0 = fmaxf(mx0, __shfl_xor_sync(0xffffffffu, mx0, 2));
        mx1 = fmaxf(mx1, __shfl_xor_sync(0xffffffffu, mx1, 1));
        mx1 = fmaxf(mx1, __shfl_xor_sync(0xffffffffu, mx1, 2));
        float mn0 = fmaxf(m0, mx0), mn1 = fmaxf(m1, mx1);
        float a0 = ex2(m0 - mn0), a1 = ex2(m1 - mn1);
        m0 = mn0; m1 = mn1;
        float s0 = 0.f, s1 = 0.f;
        #pragma unroll
        for (int nf = 0; nf < 8; nf++) {
            S[nf][0] = ex2(S[nf][0] - m0);
            S[nf][1] = ex2(S[nf][1] - m0);
            S[nf][2] = ex2(S[nf][2] - m1);
            S[nf][3] = ex2(S[nf][3] - m1);
            s0 += S[nf][0] + S[nf][1];
            s1 += S[nf][2] + S[nf][3];
        }
        s0 += __shfl_xor_sync(0xffffffffu, s0, 1);
        s0 += __shfl_xor_sync(0xffffffffu, s0, 2);
        s1 += __shfl_xor_sync(0xffffffffu, s1, 1);
        s1 += __shfl_xor_sync(0xffffffffu, s1, 2);
        l0 = l0 * a0 + s0; l1 = l1 * a1 + s1;
        #pragma unroll
        for (int df = 0; df < 8; df++) {
            O[df][0] *= a0; O[df][1] *= a0; O[df][2] *= a1; O[df][3] *= a1;
        }

        // P -> warp-private smem (half2, key-pair perm'd)
        __syncwarp();
        #pragma unroll
        for (int nf = 0; nf < 8; nf++) {
            int col = (nf >> 1) * 8 + 2 * t + (nf & 1);
            Ps[(wr + g    ) * KP + col] = pk2(S[nf][0], S[nf][1]);
            Ps[(wr + g + 8) * KP + col] = pk2(S[nf][2], S[nf][3]);
        }
        __syncwarp();

        // O += P V   (4 k16 steps x 8 df)
        #pragma unroll
        for (int kf = 0; kf < 4; kf++) {
            uint2 u0 = *(const uint2*)&Ps[(wr + g    ) * KP + kf * 8 + 2 * t];
            uint2 u1 = *(const uint2*)&Ps[(wr + g + 8) * KP + kf * 8 + 2 * t];
            #pragma unroll
            for (int df = 0; df < 8; df++) {
                uint2 bv = *(const uint2*)&Vf[(df * 8 + g) * KP + kf * 8 + 2 * t];
                mma16(O[df], u0.x, u1.x, u0.y, u1.y, bv.x, bv.y);
            }
        }
    }

    // Normalize, write g_ao as half2 (e-dim perm'd for outproj)
    float il0 = 1.f / l0, il1 = 1.f / l1;
    int r0 = i0 + wr + g, r1 = r0 + 8;
    #pragma unroll
    for (int df = 0; df < 8; df++) {
        int col = (df >> 1) * 8 + 2 * t + (df & 1);
        g_ao[(size_t)(b * L_ + r0) * D2 + h * 32 + col] = pk2(O[df][0] * il0, O[df][1] * il0);
        g_ao[(size_t)(b * L_ + r1) * D2 + h * 32 + col] = pk2(O[df][2] * il1, O[df][3] * il1);
    }
}

// ---------------------------------------------------------------------------
extern "C" void kernel_launch(void* const* d_in, const int* in_sizes, int n_in,
                              void* d_out, int out_size)
{
    const float* x     = (const float*)d_in[0];
    const float* pos   = (const float*)d_in[1];
    const float* wqkv  = (const float*)d_in[2];
    const float* wout  = (const float*)d_in[3];
    const float* bout  = (const float*)d_in[4];
    const float* lsig  = (const float*)d_in[5];
    const float* gbias = (const float*)d_in[6];
    const int*   nsp   = (const int*)d_in[7];
    float* out = (float*)d_out;

    unsigned *p_xt, *p_w1, *p_w2;
    cudaGetSymbolAddress((void**)&p_xt, g_xt);
    cudaGetSymbolAddress((void**)&p_w1, g_w1);
    cudaGetSymbolAddress((void**)&p_w2, g_w2);

    cudaFuncSetAttribute(attn_h, cudaFuncAttributeMaxDynamicSharedMemorySize, ATTN_SMEM);
    cudaFuncSetAttribute(gemm_h<NQKV, 0>, cudaFuncAttributeMaxDynamicSharedMemorySize, GEMM_SMEM);
    cudaFuncSetAttribute(gemm_h<D_, 1>, cudaFuncAttributeMaxDynamicSharedMemorySize, GEMM_SMEM);

    prep_h<<<(M_ * D_ / 16 + 255) / 256, 256>>>(x, p_xt, M_ * D_ / 16);
    prep_h<<<(NQKV * D_ / 16 + 255) / 256, 256>>>(wqkv, p_w1, NQKV * D_ / 16);
    prep_h<<<(D_ * D_ / 16 + 255) / 256, 256>>>(wout, p_w2, D_ * D_ / 16);

    gemm_h<NQKV, 0><<<dim3(NQKV / 128, M_ / 128), 256, GEMM_SMEM>>>(p_xt, p_w1, nullptr, nullptr);
    attn_h<<<dim3(L_ / 128, B_ * H_), 256, ATTN_SMEM>>>(pos, lsig, gbias, nsp);
    gemm_h<D_, 1><<<dim3(D_ / 128, M_ / 128), 256, GEMM_SMEM>>>(nullptr, p_w2, bout, out);
}

// round 9
// speedup vs baseline: 6.7542x; 1.0991x over previous
#include <cuda_runtime.h>
#include <cuda_fp16.h>

#define B_   2
#define H_   8
#define L_   2048
#define DH_  64
#define D_   512
#define M_   4096
#define NQKV 1536
#define D2   256                 // uints (half2) per row of a D_-wide matrix
#define QS_U 1048576             // uints per qkv section: B*H*L*DH/2
#define LOG2E 1.4426950408889634f

// Scratch (device globals; no allocations allowed).
// q (prescaled by 0.125*log2e), k: [B,H,L, 32 uints] PLAIN row-major (for ldmatrix)
// v: transposed per 64-key tile [B,H,L/64, 64 dh rows, 64 key halves] PLAIN
__device__ unsigned g_qkv[3 * QS_U];
__device__ unsigned g_ao[M_ * D2];       // attn out, e-dim perm'd (outproj operand)
__device__ unsigned g_xt[M_ * D2];       // x,      k-dim perm'd
__device__ unsigned g_w1[NQKV * D2];     // w_qkv,  k-dim perm'd
__device__ unsigned g_w2[D_ * D2];       // w_out,  k-dim perm'd

__device__ __forceinline__ unsigned pk2(float a, float b) {
    __half2 h = __floats2half2_rn(a, b);       // low = a
    return *(unsigned*)&h;
}
__device__ __forceinline__ unsigned pkcvt(float hi, float lo) {
    unsigned r; asm("cvt.rn.f16x2.f32 %0, %1, %2;" : "=r"(r) : "f"(hi), "f"(lo)); return r;
}
__device__ __forceinline__ unsigned ex2h2(unsigned x) {
    unsigned r; asm("ex2.approx.f16x2 %0, %1;" : "=r"(r) : "r"(x)); return r;
}
__device__ __forceinline__ float ex2(float x) {
    float r; asm("ex2.approx.f32 %0, %1;" : "=f"(r) : "f"(x)); return r;
}
__device__ __forceinline__ unsigned sptr(const void* p) {
    return (unsigned)__cvta_generic_to_shared(p);
}
__device__ __forceinline__ void ldsm4(unsigned& d0, unsigned& d1, unsigned& d2, unsigned& d3,
                                      unsigned addr) {
    asm volatile("ldmatrix.sync.aligned.m8n8.x4.shared.b16 {%0,%1,%2,%3}, [%4];"
                 : "=r"(d0), "=r"(d1), "=r"(d2), "=r"(d3) : "r"(addr));
}
#define CP16(d, s) asm volatile("cp.async.cg.shared.global [%0], [%1], 16;" :: "r"(d), "l"(s) : "memory")
#define CP8Z(d, s, sz) asm volatile("cp.async.ca.shared.global [%0], [%1], 8, %2;" :: "r"(d), "l"(s), "r"(sz) : "memory")
__device__ __forceinline__ void cp_commit() { asm volatile("cp.async.commit_group;" ::: "memory"); }
__device__ __forceinline__ void cp_wait0()  { asm volatile("cp.async.wait_group 0;" ::: "memory"); }
__device__ __forceinline__ void cp_wait1()  { asm volatile("cp.async.wait_group 1;" ::: "memory"); }

__device__ __forceinline__ void mma16(float* c,
                                      unsigned a0, unsigned a1, unsigned a2, unsigned a3,
                                      unsigned b0, unsigned b1) {
    asm volatile("mma.sync.aligned.m16n8k16.row.col.f32.f16.f16.f32 "
                 "{%0,%1,%2,%3}, {%4,%5,%6,%7}, {%8,%9}, {%0,%1,%2,%3};"
                 : "+f"(c[0]), "+f"(c[1]), "+f"(c[2]), "+f"(c[3])
                 : "r"(a0), "r"(a1), "r"(a2), "r"(a3), "r"(b0), "r"(b1));
}

// ---------------------------------------------------------------------------
// Prepass: fp32 -> half2 with per-8-pair permutation (for gemm operands only).
// ---------------------------------------------------------------------------
__global__ __launch_bounds__(256) void prep_h(const float* __restrict__ src,
                                              unsigned* __restrict__ dst, int n16)
{
    int i = blockIdx.x * blockDim.x + threadIdx.x;
    if (i >= n16) return;
    const float4* s = (const float4*)(src + (size_t)i * 16);
    float4 s0 = s[0], s1 = s[1], s2 = s[2], s3 = s[3];
    uint4 o0, o1;
    o0.x = pk2(s0.x, s0.y); o0.y = pk2(s2.x, s2.y);
    o0.z = pk2(s0.z, s0.w); o0.w = pk2(s2.z, s2.w);
    o1.x = pk2(s1.x, s1.y); o1.y = pk2(s3.x, s3.y);
    o1.z = pk2(s1.z, s1.w); o1.w = pk2(s3.z, s3.w);
    uint4* d = (uint4*)(dst + (size_t)i * 8);
    d[0] = o0; d[1] = o1;
}

// ---------------------------------------------------------------------------
// fp16 GEMM, cp.async double-buffered (permuted operands, uint2 frag loads).
// EPI=0: scatter qkv PLAIN (q prescaled; v transposed per 64-tile).
// EPI=1: A := g_ao (perm'd), write out + bias fp32.
// ---------------------------------------------------------------------------
#define GP 40
#define GEMM_SMEM (2 * 2 * 128 * GP * 4)

template <int NTOT, int EPI>
__global__ __launch_bounds__(256, 2) void gemm_h(const unsigned* __restrict__ A,
                                                 const unsigned* __restrict__ Wt,
                                                 const float* __restrict__ bias,
                                                 float* __restrict__ out)
{
    extern __shared__ unsigned gsm[];
    unsigned* As = gsm;                 // [2][128][GP]
    unsigned* Bs = gsm + 2 * 128 * GP;  // [2][128][GP]

    const int m0 = blockIdx.y * 128;
    const int n0 = blockIdx.x * 128;
    const int tid  = threadIdx.x;
    const int warp = tid >> 5, lane = tid & 31;
    const int g = lane >> 2, t = lane & 3;
    const int wm = warp >> 1, wn = warp & 1;

    const unsigned* Ap = (EPI == 1) ? (const unsigned*)g_ao : A;

    float C[2][8][4] = {};

    auto issue = [&](int ki, int buf) {
        int k0 = ki * 32;                       // uints
        unsigned* Ad = As + buf * 128 * GP;
        unsigned* Bd = Bs + buf * 128 * GP;
        #pragma unroll
        for (int p = 0; p < 4; p++) {
            int c = tid + p * 256;
            int r = c >> 3, col = (c & 7) * 4;
            CP16(sptr(&Ad[r * GP + col]), &Ap[(size_t)(m0 + r) * D2 + k0 + col]);
            CP16(sptr(&Bd[r * GP + col]), &Wt[(size_t)(n0 + r) * D2 + k0 + col]);
        }
    };

    issue(0, 0);
    cp_commit();

    for (int ki = 0; ki < 8; ki++) {
        int buf = ki & 1;
        __syncthreads();
        if (ki + 1 < 8) { issue(ki + 1, buf ^ 1); cp_commit(); cp_wait1(); }
        else            { cp_wait0(); }
        __syncthreads();

        const unsigned* Af = As + buf * 128 * GP;
        const unsigned* Bf = Bs + buf * 128 * GP;
        #pragma unroll
        for (int kk = 0; kk < 32; kk += 8) {    // 4 k16 steps
            unsigned a[2][4];
            #pragma unroll
            for (int mf = 0; mf < 2; mf++) {
                int rb = wm * 32 + mf * 16;
                uint2 u0 = *(const uint2*)&Af[(rb + g    ) * GP + kk + 2 * t];
                uint2 u1 = *(const uint2*)&Af[(rb + g + 8) * GP + kk + 2 * t];
                a[mf][0] = u0.x; a[mf][1] = u1.x; a[mf][2] = u0.y; a[mf][3] = u1.y;
            }
            #pragma unroll
            for (int nf = 0; nf < 8; nf++) {
                int nb = wn * 64 + nf * 8;
                uint2 bv = *(const uint2*)&Bf[(nb + g) * GP + kk + 2 * t];
                mma16(C[0][nf], a[0][0], a[0][1], a[0][2], a[0][3], bv.x, bv.y);
                mma16(C[1][nf], a[1][0], a[1][1], a[1][2], a[1][3], bv.x, bv.y);
            }
        }
    }

    const float qscale = 0.125f * LOG2E;

    if (EPI == 0) {
        __half* hv = (__half*)g_qkv;
        #pragma unroll
        for (int mf = 0; mf < 2; mf++) {
            int m = m0 + wm * 32 + mf * 16;
            #pragma unroll
            for (int nf = 0; nf < 8; nf++) {
                int n   = n0 + wn * 64 + nf * 8 + 2 * t;
                int sec = n >> 9;
                int h   = (n >> 6) & 7;
                int dh  = n & 63;
                #pragma unroll
                for (int rr = 0; rr < 2; rr++) {
                    int mm = m + g + rr * 8;
                    int b  = mm >> 11;
                    int l  = mm & 2047;
                    float c0v = C[mf][nf][rr * 2 + 0];
                    float c1v = C[mf][nf][rr * 2 + 1];
                    if (sec == 0) { c0v *= qscale; c1v *= qscale; }
                    if (sec < 2) {
                        // plain: [B,H,L, 32 uints], uint col = dh/2 (dh is even)
                        g_qkv[(size_t)sec * QS_U
                              + (size_t)((b * H_ + h) * L_ + l) * 32 + (dh >> 1)] = pk2(c0v, c1v);
                    } else {
                        // V^T plain: [tile][dh row][key col] halves
                        size_t vb2 = (size_t)2 * QS_U * 2
                                   + (size_t)(b * H_ + h) * L_ * DH_
                                   + (size_t)(l >> 6) * 4096 + (l & 63);
                        hv[vb2 + (size_t)dh * 64]       = __float2half_rn(c0v);
                        hv[vb2 + (size_t)(dh + 1) * 64] = __float2half_rn(c1v);
                    }
                }
            }
        }
    } else {
        #pragma unroll
        for (int mf = 0; mf < 2; mf++) {
            int m = m0 + wm * 32 + mf * 16;
            #pragma unroll
            for (int nf = 0; nf < 8; nf++) {
                int n = n0 + wn * 64 + nf * 8 + 2 * t;
                float b0v = bias[n], b1v = bias[n + 1];
                #pragma unroll
                for (int rr = 0; rr < 2; rr++) {
                    int mm = m + g + rr * 8;
                    float2 v;
                    v.x = C[mf][nf][rr * 2 + 0] + b0v;
                    v.y = C[mf][nf][rr * 2 + 1] + b1v;
                    *(float2*)&out[(size_t)mm * NTOT + n] = v;
                }
            }
        }
    }
}

// ---------------------------------------------------------------------------
// Flash attention: ldmatrix fragments, register-resident P, f16x2 exp,
// tensor-core row sums, rescale skipping.
// ---------------------------------------------------------------------------
#define KP 36
#define ATTN_SMEM ((2 * 64 * KP * 2 + 128 * KP) * 4 + 128 * 8 + 2 * 64 * 8)

__global__ __launch_bounds__(256, 2) void attn_h(const float* __restrict__ pos,
                                                 const float* __restrict__ log_sigma,
                                                 const float* __restrict__ gbias_p,
                                                 const int*   __restrict__ nsp)
{
    extern __shared__ unsigned smA[];
    unsigned* Ks = smA;                   // [2][64][KP]
    unsigned* Vs = smA + 2 * 64 * KP;     // [2][64][KP]  (V^T tiles)
    unsigned* Qs = smA + 4 * 64 * KP;     // [128][KP]
    float2* qpos = (float2*)(Qs + 128 * KP);
    float2* kpos = qpos + 128;

    const int i0 = blockIdx.x * 128;
    const int bh = blockIdx.y;
    const int b  = bh >> 3, h = bh & 7;
    const int Ls = *nsp;
    const float gb2 = (*gbias_p) * LOG2E;
    const float nc2 = -0.5f * __expf(-2.0f * log_sigma[h]) * LOG2E;

    const int tid  = threadIdx.x;
    const int warp = tid >> 5, lane = tid & 31;
    const int g = lane >> 2, t = lane & 3;
    const int wr = warp * 16;

    const unsigned* qb = g_qkv + (size_t)(b * H_ + h) * L_ * 32;
    const unsigned* kb = g_qkv + (size_t)QS_U + (size_t)(b * H_ + h) * L_ * 32;
    const unsigned* vb = g_qkv + 2 * (size_t)QS_U + (size_t)(b * H_ + h) * L_ * 32;

    // Stage Q tile (128 rows x 32 uints) into Qs
    #pragma unroll
    for (int p = 0; p < 4; p++) {
        int c = tid + p * 256;
        int r = c >> 3, c4 = (c & 7) * 4;
        *(uint4*)&Qs[r * KP + c4] = *(const uint4*)&qb[(size_t)(i0 + r) * 32 + c4];
    }
    if (tid < 128) {
        int iG = i0 + tid;
        float2 v = make_float2(0.f, 0.f);
        if (iG < Ls) v = *(const float2*)&pos[(size_t)(b * Ls + iG) * 2];
        qpos[tid] = v;
    }
    __syncthreads();

    // Q A-fragments via ldmatrix (once)
    unsigned qf[4][4];
    {
        int qrow = wr + ((lane >> 3) & 1) * 8 + (lane & 7);
        int qcol = (lane >> 4) << 2;
        #pragma unroll
        for (int ks = 0; ks < 4; ks++)
            ldsm4(qf[ks][0], qf[ks][1], qf[ks][2], qf[ks][3],
                  sptr(&Qs[qrow * KP + ks * 8 + qcol]));
    }

    float qx0, qy0, qx1, qy1; bool iin0, iin1;
    {
        int r0 = i0 + wr + g;
        float2 p0 = qpos[wr + g], p1 = qpos[wr + g + 8];
        qx0 = p0.x; qy0 = p0.y; qx1 = p1.x; qy1 = p1.y;
        iin0 = r0 < Ls; iin1 = (r0 + 8) < Ls;
    }

    // per-lane ldmatrix offsets for K/V B-fragments
    const int lrow8 = ((lane >> 4) << 3) + (lane & 7);
    const int lsel  = ((lane >> 3) & 1) * 4;

    auto issue = [&](int jt, int buf) {
        const unsigned* kt = kb + (size_t)jt * 2048;   // 64 rows x 32 uints
        const unsigned* vt = vb + (size_t)jt * 2048;
        unsigned* Kd = Ks + buf * 64 * KP;
        unsigned* Vd = Vs + buf * 64 * KP;
        #pragma unroll
        for (int p = 0; p < 2; p++) {
            int c = tid + p * 256;
            int r = c >> 3, c4 = (c & 7) * 4;
            CP16(sptr(&Kd[r * KP + c4]), kt + r * 32 + c4);
            CP16(sptr(&Vd[r * KP + c4]), vt + r * 32 + c4);
        }
        if (tid < 64) {
            int jG = jt * 64 + tid;
            CP8Z(sptr(&kpos[buf * 64 + tid]), &pos[(size_t)(b * Ls + jG) * 2],
                 (jG < Ls) ? 8u : 0u);
        }
    };

    float O[8][4] = {};
    float O8[4] = {};                 // ones-column fragment: l lives in c0 (t=0)
    float m0 = -1e30f, m1 = -1e30f;
    const bool i_allsp = (i0 + 128) <= Ls;
    const bool i_allout = i0 >= Ls;
    const unsigned ones2 = (g == 0) ? 0x3C003C00u : 0u;

    issue(0, 0);
    cp_commit();

    for (int jt = 0; jt < 32; jt++) {
        int buf = jt & 1;
        __syncthreads();
        if (jt + 1 < 32) { issue(jt + 1, buf ^ 1); cp_commit(); cp_wait1(); }
        else             { cp_wait0(); }
        __syncthreads();

        const unsigned* Kf = Ks + buf * 64 * KP;
        const unsigned* Vf = Vs + buf * 64 * KP;
        const float2*   kp = kpos + buf * 64;
        const int j0 = jt * 64;

        // S = Q K^T  via ldmatrix B-fragments
        float S[8][4] = {};
        #pragma unroll
        for (int f = 0; f < 4; f++) {
            #pragma unroll
            for (int ks = 0; ks < 4; ks++) {
                unsigned d0, d1, d2, d3;
                ldsm4(d0, d1, d2, d3,
                      sptr(&Kf[(16 * f + lrow8) * KP + 8 * ks + lsel]));
                mma16(S[2*f],   qf[ks][0], qf[ks][1], qf[ks][2], qf[ks][3], d0, d1);
                mma16(S[2*f+1], qf[ks][0], qf[ks][1], qf[ks][2], qf[ks][3], d2, d3);
            }
        }

        // Bias (3 paths) — S already includes scale*log2e via prescaled q
        if (i_allsp && (j0 + 64) <= Ls) {
            #pragma unroll
            for (int nf = 0; nf < 8; nf++) {
                int c0 = nf * 8 + 2 * t;
                float2 kp0 = kp[c0], kp1 = kp[c0 + 1];
                float dx, dy, dd;
                dx = qx0 - kp0.x; dy = qy0 - kp0.y; dd = fmaf(dy, dy, dx * dx);
                S[nf][0] = fmaf(dd, nc2, S[nf][0]);
                dx = qx0 - kp1.x; dy = qy0 - kp1.y; dd = fmaf(dy, dy, dx * dx);
                S[nf][1] = fmaf(dd, nc2, S[nf][1]);
                dx = qx1 - kp0.x; dy = qy1 - kp0.y; dd = fmaf(dy, dy, dx * dx);
                S[nf][2] = fmaf(dd, nc2, S[nf][2]);
                dx = qx1 - kp1.x; dy = qy1 - kp1.y; dd = fmaf(dy, dy, dx * dx);
                S[nf][3] = fmaf(dd, nc2, S[nf][3]);
            }
        } else if (j0 >= Ls || i_allout) {
            #pragma unroll
            for (int nf = 0; nf < 8; nf++) {
                S[nf][0] += gb2; S[nf][1] += gb2; S[nf][2] += gb2; S[nf][3] += gb2;
            }
        } else {
            #pragma unroll
            for (int nf = 0; nf < 8; nf++) {
                int c0 = nf * 8 + 2 * t;
                int jg0 = j0 + c0;
                float2 kp0 = kp[c0], kp1 = kp[c0 + 1];
                bool jin0 = jg0 < Ls, jin1 = (jg0 + 1) < Ls;
                float dx, dy, dd;
                dx = qx0 - kp0.x; dy = qy0 - kp0.y; dd = fmaf(dy, dy, dx * dx);
                S[nf][0] += (iin0 && jin0) ? dd * nc2 : gb2;
                dx = qx0 - kp1.x; dy = qy0 - kp1.y; dd = fmaf(dy, dy, dx * dx);
                S[nf][1] += (iin0 && jin1) ? dd * nc2 : gb2;
                dx = qx1 - kp0.x; dy = qy1 - kp0.y; dd = fmaf(dy, dy, dx * dx);
                S[nf][2] += (iin1 && jin0) ? dd * nc2 : gb2;
                dx = qx1 - kp1.x; dy = qy1 - kp1.y; dd = fmaf(dy, dy, dx * dx);
                S[nf][3] += (iin1 && jin1) ? dd * nc2 : gb2;
            }
        }

        // Online softmax (base 2), rescale skipped when max unchanged
        float mx0 = -1e30f, mx1 = -1e30f;
        #pragma unroll
        for (int nf = 0; nf < 8; nf++) {
            mx0 = fmaxf(mx0, fmaxf(S[nf][0], S[nf][1]));
            mx1 = fmaxf(mx1, fmaxf(S[nf][2], S[nf][3]));
        }
        mx0 = fmaxf(mx0, __shfl_xor_sync(0xffffffffu, mx0, 1));
        mx0 = fmaxf(mx0, __shfl_xor_sync(0xffffffffu, mx0, 2));
        mx1 = fmaxf(mx1, __shfl_xor_sync(0xffffffffu, mx1, 1));
        mx1 = fmaxf(mx1, __shfl_xor_sync(0xffffffffu, mx1, 2));
        float mn0 = fmaxf(m0, mx0), mn1 = fmaxf(m1, mx1);
        bool stay = (mn0 == m0) && (mn1 == m1);
        if (!__all_sync(0xffffffffu, stay)) {
            float a0 = ex2(m0 - mn0), a1 = ex2(m1 - mn1);
            #pragma unroll
            for (int df = 0; df < 8; df++) {
                O[df][0] *= a0; O[df][1] *= a0; O[df][2] *= a1; O[df][3] *= a1;
            }
            O8[0] *= a0; O8[1] *= a0; O8[2] *= a1; O8[3] *= a1;
        }
        m0 = mn0; m1 = mn1;

        // P = 2^(S-m) in packed half2 — directly the PV A-fragments
        unsigned ph[8], phh[8];
        #pragma unroll
        for (int nf = 0; nf < 8; nf++) {
            float e0 = S[nf][0] - m0, e1 = S[nf][1] - m0;
            float e2 = S[nf][2] - m1, e3 = S[nf][3] - m1;
            ph[nf]  = ex2h2(pkcvt(e1, e0));
            phh[nf] = ex2h2(pkcvt(e3, e2));
        }

        // O += P V  via ldmatrix B-fragments (V^T tile)
        #pragma unroll
        for (int f = 0; f < 4; f++) {
            #pragma unroll
            for (int ks = 0; ks < 4; ks++) {
                unsigned d0, d1, d2, d3;
                ldsm4(d0, d1, d2, d3,
                      sptr(&Vf[(16 * f + lrow8) * KP + 8 * ks + lsel]));
                mma16(O[2*f],   ph[2*ks], phh[2*ks], ph[2*ks+1], phh[2*ks+1], d0, d1);
                mma16(O[2*f+1], ph[2*ks], phh[2*ks], ph[2*ks+1], phh[2*ks+1], d2, d3);
            }
        }
        // l += P @ ones  (virtual V column of 1s; no memory)
        #pragma unroll
        for (int ks = 0; ks < 4; ks++)
            mma16(O8, ph[2*ks], phh[2*ks], ph[2*ks+1], phh[2*ks+1], ones2, ones2);
    }

    // l from t=0 lane of each quad; normalize; write g_ao (e-dim perm'd)
    float l0 = __shfl_sync(0xffffffffu, O8[0], lane & ~3);
    float l1 = __shfl_sync(0xffffffffu, O8[2], lane & ~3);
    float il0 = 1.f / l0, il1 = 1.f / l1;
    int r0 = i0 + wr + g, r1 = r0 + 8;
    #pragma unroll
    for (int df = 0; df < 8; df++) {
        int col = (df >> 1) * 8 + 2 * t + (df & 1);
        g_ao[(size_t)(b * L_ + r0) * D2 + h * 32 + col] = pk2(O[df][0] * il0, O[df][1] * il0);
        g_ao[(size_t)(b * L_ + r1) * D2 + h * 32 + col] = pk2(O[df][2] * il1, O[df][3] * il1);
    }
}

// ---------------------------------------------------------------------------
extern "C" void kernel_launch(void* const* d_in, const int* in_sizes, int n_in,
                              void* d_out, int out_size)
{
    const float* x     = (const float*)d_in[0];
    const float* pos   = (const float*)d_in[1];
    const float* wqkv  = (const float*)d_in[2];
    const float* wout  = (const float*)d_in[3];
    const float* bout  = (const float*)d_in[4];
    const float* lsig  = (const float*)d_in[5];
    const float* gbias = (const float*)d_in[6];
    const int*   nsp   = (const int*)d_in[7];
    float* out = (float*)d_out;

    unsigned *p_xt, *p_w1, *p_w2;
    cudaGetSymbolAddress((void**)&p_xt, g_xt);
    cudaGetSymbolAddress((void**)&p_w1, g_w1);
    cudaGetSymbolAddress((void**)&p_w2, g_w2);

    cudaFuncSetAttribute(attn_h, cudaFuncAttributeMaxDynamicSharedMemorySize, ATTN_SMEM);
    cudaFuncSetAttribute(gemm_h<NQKV, 0>, cudaFuncAttributeMaxDynamicSharedMemorySize, GEMM_SMEM);
    cudaFuncSetAttribute(gemm_h<D_, 1>, cudaFuncAttributeMaxDynamicSharedMemorySize, GEMM_SMEM);

    prep_h<<<(M_ * D_ / 16 + 255) / 256, 256>>>(x, p_xt, M_ * D_ / 16);
    prep_h<<<(NQKV * D_ / 16 + 255) / 256, 256>>>(wqkv, p_w1, NQKV * D_ / 16);
    prep_h<<<(D_ * D_ / 16 + 255) / 256, 256>>>(wout, p_w2, D_ * D_ / 16);

    gemm_h<NQKV, 0><<<dim3(NQKV / 128, M_ / 128), 256, GEMM_SMEM>>>(p_xt, p_w1, nullptr, nullptr);
    attn_h<<<dim3(L_ / 128, B_ * H_), 256, ATTN_SMEM>>>(pos, lsig, gbias, nsp);
    gemm_h<D_, 1><<<dim3(D_ / 128, M_ / 128), 256, GEMM_SMEM>>>(nullptr, p_w2, bout, out);
}

// round 10
// speedup vs baseline: 6.9738x; 1.0325x over previous
#include <cuda_runtime.h>
#include <cuda_fp16.h>

#define B_   2
#define H_   8
#define L_   2048
#define DH_  64
#define D_   512
#define M_   4096
#define NQKV 1536
#define D2   256                 // uints (half2) per row of a D_-wide matrix
#define QS_U 1048576             // uints per qkv section: B*H*L*DH/2
#define LOG2E 1.4426950408889634f

// Scratch (device globals; no allocations allowed). ALL layouts PLAIN now
// (ldmatrix handles fragment shuffling).
// q (prescaled by 0.125*log2e), k: [B,H,L, 32 uints]
// v: transposed per 64-key tile [B,H,L/64, 64 dh rows, 64 key halves]
__device__ unsigned g_qkv[3 * QS_U];
__device__ unsigned g_ao[M_ * D2];       // attn out (plain)
__device__ unsigned g_xt[M_ * D2];       // x converted
__device__ unsigned g_w1[NQKV * D2];     // w_qkv converted
__device__ unsigned g_w2[D_ * D2];       // w_out converted

__device__ __forceinline__ unsigned pk2(float a, float b) {
    __half2 h = __floats2half2_rn(a, b);       // low = a
    return *(unsigned*)&h;
}
__device__ __forceinline__ unsigned pkcvt(float hi, float lo) {
    unsigned r; asm("cvt.rn.f16x2.f32 %0, %1, %2;" : "=r"(r) : "f"(hi), "f"(lo)); return r;
}
__device__ __forceinline__ unsigned ex2h2(unsigned x) {
    unsigned r; asm("ex2.approx.f16x2 %0, %1;" : "=r"(r) : "r"(x)); return r;
}
__device__ __forceinline__ float ex2(float x) {
    float r; asm("ex2.approx.f32 %0, %1;" : "=f"(r) : "f"(x)); return r;
}
__device__ __forceinline__ unsigned sptr(const void* p) {
    return (unsigned)__cvta_generic_to_shared(p);
}
__device__ __forceinline__ void ldsm4(unsigned& d0, unsigned& d1, unsigned& d2, unsigned& d3,
                                      unsigned addr) {
    asm volatile("ldmatrix.sync.aligned.m8n8.x4.shared.b16 {%0,%1,%2,%3}, [%4];"
                 : "=r"(d0), "=r"(d1), "=r"(d2), "=r"(d3) : "r"(addr));
}
#define CP16(d, s) asm volatile("cp.async.cg.shared.global [%0], [%1], 16;" :: "r"(d), "l"(s) : "memory")
__device__ __forceinline__ void cp_commit() { asm volatile("cp.async.commit_group;" ::: "memory"); }
__device__ __forceinline__ void cp_wait0()  { asm volatile("cp.async.wait_group 0;" ::: "memory"); }
__device__ __forceinline__ void cp_wait1()  { asm volatile("cp.async.wait_group 1;" ::: "memory"); }

__device__ __forceinline__ void mma16(float* c,
                                      unsigned a0, unsigned a1, unsigned a2, unsigned a3,
                                      unsigned b0, unsigned b1) {
    asm volatile("mma.sync.aligned.m16n8k16.row.col.f32.f16.f16.f32 "
                 "{%0,%1,%2,%3}, {%4,%5,%6,%7}, {%8,%9}, {%0,%1,%2,%3};"
                 : "+f"(c[0]), "+f"(c[1]), "+f"(c[2]), "+f"(c[3])
                 : "r"(a0), "r"(a1), "r"(a2), "r"(a3), "r"(b0), "r"(b1));
}

// ---------------------------------------------------------------------------
// Fused prepass: fp32 -> half2 plain convert for x, w_qkv, w_out (one launch).
// ---------------------------------------------------------------------------
#define N16_X  (M_ * D_ / 16)
#define N16_W1 (NQKV * D_ / 16)
#define N16_W2 (D_ * D_ / 16)
#define N16_TOT (N16_X + N16_W1 + N16_W2)

__global__ __launch_bounds__(256) void prep_all(const float* __restrict__ x,
                                                const float* __restrict__ wqkv,
                                                const float* __restrict__ wout)
{
    int i = blockIdx.x * blockDim.x + threadIdx.x;
    if (i >= N16_TOT) return;
    const float* src;
    unsigned* dst;
    if (i < N16_X)                { src = x    + (size_t)i * 16;            dst = g_xt + (size_t)i * 8; }
    else if (i < N16_X + N16_W1)  { size_t j = i - N16_X;
                                    src = wqkv + j * 16;                     dst = g_w1 + j * 8; }
    else                          { size_t j = i - N16_X - N16_W1;
                                    src = wout + j * 16;                     dst = g_w2 + j * 8; }
    const float4* s = (const float4*)src;
    float4 s0 = s[0], s1 = s[1], s2 = s[2], s3 = s[3];
    uint4 o0, o1;
    o0.x = pk2(s0.x, s0.y); o0.y = pk2(s0.z, s0.w);
    o0.z = pk2(s1.x, s1.y); o0.w = pk2(s1.z, s1.w);
    o1.x = pk2(s2.x, s2.y); o1.y = pk2(s2.z, s2.w);
    o1.z = pk2(s3.x, s3.y); o1.w = pk2(s3.z, s3.w);
    uint4* d = (uint4*)dst;
    d[0] = o0; d[1] = o1;
}

// ---------------------------------------------------------------------------
// fp16 GEMM, cp.async double-buffered, ldmatrix fragments (plain layouts).
// EPI=0: scatter qkv PLAIN.  EPI=1: A := g_ao, write out + bias fp32.
// ---------------------------------------------------------------------------
#define GP 36
#define GEMM_SMEM (2 * 2 * 128 * GP * 4)

template <int NTOT, int EPI>
__global__ __launch_bounds__(256, 2) void gemm_h(const unsigned* __restrict__ A,
                                                 const unsigned* __restrict__ Wt,
                                                 const float* __restrict__ bias,
                                                 float* __restrict__ out)
{
    extern __shared__ unsigned gsm[];
    unsigned* As = gsm;                 // [2][128][GP]
    unsigned* Bs = gsm + 2 * 128 * GP;  // [2][128][GP]

    const int m0 = blockIdx.y * 128;
    const int n0 = blockIdx.x * 128;
    const int tid  = threadIdx.x;
    const int warp = tid >> 5, lane = tid & 31;
    const int g = lane >> 2, t = lane & 3;
    const int wm = warp >> 1, wn = warp & 1;

    // ldmatrix per-lane offsets (patterns validated in attention kernel)
    const int arow = ((lane >> 3) & 1) * 8 + (lane & 7);
    const int acol = (lane >> 4) << 2;                    // uints
    const int brow = ((lane >> 4) << 3) + (lane & 7);
    const int bcol = ((lane >> 3) & 1) * 4;               // uints

    const unsigned* Ap = (EPI == 1) ? (const unsigned*)g_ao : A;

    float C[2][8][4] = {};

    auto issue = [&](int ki, int buf) {
        int k0 = ki * 32;                       // uints
        unsigned* Ad = As + buf * 128 * GP;
        unsigned* Bd = Bs + buf * 128 * GP;
        #pragma unroll
        for (int p = 0; p < 4; p++) {
            int c = tid + p * 256;
            int r = c >> 3, col = (c & 7) * 4;
            CP16(sptr(&Ad[r * GP + col]), &Ap[(size_t)(m0 + r) * D2 + k0 + col]);
            CP16(sptr(&Bd[r * GP + col]), &Wt[(size_t)(n0 + r) * D2 + k0 + col]);
        }
    };

    issue(0, 0);
    cp_commit();

    for (int ki = 0; ki < 8; ki++) {
        int buf = ki & 1;
        __syncthreads();
        if (ki + 1 < 8) { issue(ki + 1, buf ^ 1); cp_commit(); cp_wait1(); }
        else            { cp_wait0(); }
        __syncthreads();

        const unsigned* Af = As + buf * 128 * GP;
        const unsigned* Bf = Bs + buf * 128 * GP;
        #pragma unroll
        for (int ks = 0; ks < 4; ks++) {         // 4 k16 steps per chunk
            unsigned a[2][4];
            #pragma unroll
            for (int mf = 0; mf < 2; mf++)
                ldsm4(a[mf][0], a[mf][1], a[mf][2], a[mf][3],
                      sptr(&Af[(wm * 32 + mf * 16 + arow) * GP + ks * 8 + acol]));
            #pragma unroll
            for (int f = 0; f < 4; f++) {
                unsigned d0, d1, d2, d3;
                ldsm4(d0, d1, d2, d3,
                      sptr(&Bf[(wn * 64 + 16 * f + brow) * GP + ks * 8 + bcol]));
                mma16(C[0][2*f],   a[0][0], a[0][1], a[0][2], a[0][3], d0, d1);
                mma16(C[0][2*f+1], a[0][0], a[0][1], a[0][2], a[0][3], d2, d3);
                mma16(C[1][2*f],   a[1][0], a[1][1], a[1][2], a[1][3], d0, d1);
                mma16(C[1][2*f+1], a[1][0], a[1][1], a[1][2], a[1][3], d2, d3);
            }
        }
    }

    const float qscale = 0.125f * LOG2E;

    if (EPI == 0) {
        __half* hv = (__half*)g_qkv;
        #pragma unroll
        for (int mf = 0; mf < 2; mf++) {
            int m = m0 + wm * 32 + mf * 16;
            #pragma unroll
            for (int nf = 0; nf < 8; nf++) {
                int n   = n0 + wn * 64 + nf * 8 + 2 * t;
                int sec = n >> 9;
                int h   = (n >> 6) & 7;
                int dh  = n & 63;
                #pragma unroll
                for (int rr = 0; rr < 2; rr++) {
                    int mm = m + g + rr * 8;
                    int b  = mm >> 11;
                    int l  = mm & 2047;
                    float c0v = C[mf][nf][rr * 2 + 0];
                    float c1v = C[mf][nf][rr * 2 + 1];
                    if (sec == 0) { c0v *= qscale; c1v *= qscale; }
                    if (sec < 2) {
                        g_qkv[(size_t)sec * QS_U
                              + (size_t)((b * H_ + h) * L_ + l) * 32 + (dh >> 1)] = pk2(c0v, c1v);
                    } else {
                        size_t vb2 = (size_t)2 * QS_U * 2
                                   + (size_t)(b * H_ + h) * L_ * DH_
                                   + (size_t)(l >> 6) * 4096 + (l & 63);
                        hv[vb2 + (size_t)dh * 64]       = __float2half_rn(c0v);
                        hv[vb2 + (size_t)(dh + 1) * 64] = __float2half_rn(c1v);
                    }
                }
            }
        }
    } else {
        #pragma unroll
        for (int mf = 0; mf < 2; mf++) {
            int m = m0 + wm * 32 + mf * 16;
            #pragma unroll
            for (int nf = 0; nf < 8; nf++) {
                int n = n0 + wn * 64 + nf * 8 + 2 * t;
                float b0v = bias[n], b1v = bias[n + 1];
                #pragma unroll
                for (int rr = 0; rr < 2; rr++) {
                    int mm = m + g + rr * 8;
                    float2 v;
                    v.x = C[mf][nf][rr * 2 + 0] + b0v;
                    v.y = C[mf][nf][rr * 2 + 1] + b1v;
                    *(float2*)&out[(size_t)mm * NTOT + n] = v;
                }
            }
        }
    }
}

// ---------------------------------------------------------------------------
// Flash attention: ldmatrix frags, register P, f16x2 exp, tensor-core row
// sums, rescale skipping, FACTORED bias (softmax shift-invariant form).
// ---------------------------------------------------------------------------
#define KP 36
#define ATTN_SMEM ((4 * 64 * KP + 128 * KP) * 4 + 128 * 8 + 2 * 64 * 16)

__global__ __launch_bounds__(256, 2) void attn_h(const float* __restrict__ pos,
                                                 const float* __restrict__ log_sigma,
                                                 const float* __restrict__ gbias_p,
                                                 const int*   __restrict__ nsp)
{
    extern __shared__ unsigned smA[];
    unsigned* Ks = smA;                   // [2][64][KP]
    unsigned* Vs = smA + 2 * 64 * KP;     // [2][64][KP]  (V^T tiles)
    unsigned* Qs = smA + 4 * 64 * KP;     // [128][KP]
    float2* qpos = (float2*)(Qs + 128 * KP);     // 128
    float4* kq   = (float4*)(qpos + 128);        // [2][64]: kx, ky, nc2*|p|^2, 0

    const int i0 = blockIdx.x * 128;
    const int bh = blockIdx.y;
    const int b  = bh >> 3, h = bh & 7;
    const int Ls = *nsp;
    const float gb2 = (*gbias_p) * LOG2E;
    const float nc2 = -0.5f * __expf(-2.0f * log_sigma[h]) * LOG2E;

    const int tid  = threadIdx.x;
    const int warp = tid >> 5, lane = tid & 31;
    const int g = lane >> 2, t = lane & 3;
    const int wr = warp * 16;

    const unsigned* qb = g_qkv + (size_t)(b * H_ + h) * L_ * 32;
    const unsigned* kb = g_qkv + (size_t)QS_U + (size_t)(b * H_ + h) * L_ * 32;
    const unsigned* vb = g_qkv + 2 * (size_t)QS_U + (size_t)(b * H_ + h) * L_ * 32;

    // Stage Q tile + qpos + kq tile 0
    #pragma unroll
    for (int p = 0; p < 4; p++) {
        int c = tid + p * 256;
        int r = c >> 3, c4 = (c & 7) * 4;
        *(uint4*)&Qs[r * KP + c4] = *(const uint4*)&qb[(size_t)(i0 + r) * 32 + c4];
    }
    if (tid < 128) {
        int iG = i0 + tid;
        float2 v = make_float2(0.f, 0.f);
        if (iG < Ls) v = *(const float2*)&pos[(size_t)(b * Ls + iG) * 2];
        qpos[tid] = v;
    }
    if (tid < 64) {
        float2 p = make_float2(0.f, 0.f);
        if (tid < Ls) p = *(const float2*)&pos[(size_t)(b * Ls + tid) * 2];
        kq[tid] = make_float4(p.x, p.y, nc2 * (p.x * p.x + p.y * p.y), 0.f);
    }
    __syncthreads();

    // Q A-fragments via ldmatrix (once)
    unsigned qf[4][4];
    {
        int qrow = wr + ((lane >> 3) & 1) * 8 + (lane & 7);
        int qcol = (lane >> 4) << 2;
        #pragma unroll
        for (int ks = 0; ks < 4; ks++)
            ldsm4(qf[ks][0], qf[ks][1], qf[ks][2], qf[ks][3],
                  sptr(&Qs[qrow * KP + ks * 8 + qcol]));
    }

    // Row constants for factored bias
    float cx0, cy0, cx1, cy1, ga0, ga1;
    bool iin0, iin1;
    {
        int r0 = i0 + wr + g;
        float2 p0 = qpos[wr + g], p1 = qpos[wr + g + 8];
        cx0 = -2.f * nc2 * p0.x; cy0 = -2.f * nc2 * p0.y;
        cx1 = -2.f * nc2 * p1.x; cy1 = -2.f * nc2 * p1.y;
        ga0 = gb2 - nc2 * (p0.x * p0.x + p0.y * p0.y);
        ga1 = gb2 - nc2 * (p1.x * p1.x + p1.y * p1.y);
        iin0 = r0 < Ls; iin1 = (r0 + 8) < Ls;
    }

    const int lrow8 = ((lane >> 4) << 3) + (lane & 7);
    const int lsel  = ((lane >> 3) & 1) * 4;

    auto issue = [&](int jt, int buf) {
        const unsigned* kt = kb + (size_t)jt * 2048;
        const unsigned* vt = vb + (size_t)jt * 2048;
        unsigned* Kd = Ks + buf * 64 * KP;
        unsigned* Vd = Vs + buf * 64 * KP;
        #pragma unroll
        for (int p = 0; p < 2; p++) {
            int c = tid + p * 256;
            int r = c >> 3, c4 = (c & 7) * 4;
            CP16(sptr(&Kd[r * KP + c4]), kt + r * 32 + c4);
            CP16(sptr(&Vd[r * KP + c4]), vt + r * 32 + c4);
        }
    };

    float O[8][4] = {};
    float O8[4] = {};
    float m0 = -1e30f, m1 = -1e30f;
    const bool i_allsp = (i0 + 128) <= Ls;
    const bool i_allout = i0 >= Ls;
    const unsigned ones2 = (g == 0) ? 0x3C003C00u : 0u;

    issue(0, 0);
    cp_commit();

    for (int jt = 0; jt < 32; jt++) {
        int buf = jt & 1;
        __syncthreads();
        bool pref = (jt + 1 < 32);
        if (pref) { issue(jt + 1, buf ^ 1); cp_commit(); }
        // prefetch next tile's k positions (LDG overlapped with this tile)
        float2 pp = make_float2(0.f, 0.f);
        if (pref && tid < 64) {
            int jG = (jt + 1) * 64 + tid;
            if (jG < Ls) pp = *(const float2*)&pos[(size_t)(b * Ls + jG) * 2];
        }
        if (pref) cp_wait1(); else cp_wait0();
        __syncthreads();

        const unsigned* Kf = Ks + buf * 64 * KP;
        const unsigned* Vf = Vs + buf * 64 * KP;
        const float4*   kc = kq + buf * 64;
        const int j0 = jt * 64;

        // S = Q K^T
        float S[8][4] = {};
        #pragma unroll
        for (int f = 0; f < 4; f++) {
            #pragma unroll
            for (int ks = 0; ks < 4; ks++) {
                unsigned d0, d1, d2, d3;
                ldsm4(d0, d1, d2, d3,
                      sptr(&Kf[(16 * f + lrow8) * KP + 8 * ks + lsel]));
                mma16(S[2*f],   qf[ks][0], qf[ks][1], qf[ks][2], qf[ks][3], d0, d1);
                mma16(S[2*f+1], qf[ks][0], qf[ks][1], qf[ks][2], qf[ks][3], d2, d3);
            }
        }

        // Factored bias (scores shifted by -nc2|pi|^2; softmax-invariant)
        if (i_allsp && (j0 + 64) <= Ls) {
            #pragma unroll
            for (int nf = 0; nf < 8; nf++) {
                int c0 = nf * 8 + 2 * t;
                float4 k0 = kc[c0], k1 = kc[c0 + 1];
                S[nf][0] = fmaf(cx0, k0.x, fmaf(cy0, k0.y, S[nf][0] + k0.z));
                S[nf][1] = fmaf(cx0, k1.x, fmaf(cy0, k1.y, S[nf][1] + k1.z));
                S[nf][2] = fmaf(cx1, k0.x, fmaf(cy1, k0.y, S[nf][2] + k0.z));
                S[nf][3] = fmaf(cx1, k1.x, fmaf(cy1, k1.y, S[nf][3] + k1.z));
            }
        } else if (j0 >= Ls || i_allout) {
            #pragma unroll
            for (int nf = 0; nf < 8; nf++) {
                S[nf][0] += ga0; S[nf][1] += ga0; S[nf][2] += ga1; S[nf][3] += ga1;
            }
        } else {
            #pragma unroll
            for (int nf = 0; nf < 8; nf++) {
                int c0 = nf * 8 + 2 * t;
                int jg0 = j0 + c0;
                float4 k0 = kc[c0], k1 = kc[c0 + 1];
                bool jin0 = jg0 < Ls, jin1 = (jg0 + 1) < Ls;
                S[nf][0] = (iin0 && jin0)
                    ? fmaf(cx0, k0.x, fmaf(cy0, k0.y, S[nf][0] + k0.z)) : S[nf][0] + ga0;
                S[nf][1] = (iin0 && jin1)
                    ? fmaf(cx0, k1.x, fmaf(cy0, k1.y, S[nf][1] + k1.z)) : S[nf][1] + ga0;
                S[nf][2] = (iin1 && jin0)
                    ? fmaf(cx1, k0.x, fmaf(cy1, k0.y, S[nf][2] + k0.z)) : S[nf][2] + ga1;
                S[nf][3] = (iin1 && jin1)
                    ? fmaf(cx1, k1.x, fmaf(cy1, k1.y, S[nf][3] + k1.z)) : S[nf][3] + ga1;
            }
        }

        // Online softmax (base 2), rescale skipped when max unchanged
        float mx0 = -1e30f, mx1 = -1e30f;
        #pragma unroll
        for (int nf = 0; nf < 8; nf++) {
            mx0 = fmaxf(mx0, fmaxf(S[nf][0], S[nf][1]));
            mx1 = fmaxf(mx1, fmaxf(S[nf][2], S[nf][3]));
        }
        mx0 = fmaxf(mx0, __shfl_xor_sync(0xffffffffu, mx0, 1));
        mx0 = fmaxf(mx0, __shfl_xor_sync(0xffffffffu, mx0, 2));
        mx1 = fmaxf(mx1, __shfl_xor_sync(0xffffffffu, mx1, 1));
        mx1 = fmaxf(mx1, __shfl_xor_sync(0xffffffffu, mx1, 2));
        float mn0 = fmaxf(m0, mx0), mn1 = fmaxf(m1, mx1);
        bool stay = (mn0 == m0) && (mn1 == m1);
        if (!__all_sync(0xffffffffu, stay)) {
            float a0 = ex2(m0 - mn0), a1 = ex2(m1 - mn1);
            #pragma unroll
            for (int df = 0; df < 8; df++) {
                O[df][0] *= a0; O[df][1] *= a0; O[df][2] *= a1; O[df][3] *= a1;
            }
            O8[0] *= a0; O8[1] *= a0; O8[2] *= a1; O8[3] *= a1;
        }
        m0 = mn0; m1 = mn1;

        // P = 2^(S-m) packed half2 — directly the PV A-fragments
        unsigned ph[8], phh[8];
        #pragma unroll
        for (int nf = 0; nf < 8; nf++) {
            float e0 = S[nf][0] - m0, e1 = S[nf][1] - m0;
            float e2 = S[nf][2] - m1, e3 = S[nf][3] - m1;
            ph[nf]  = ex2h2(pkcvt(e1, e0));
            phh[nf] = ex2h2(pkcvt(e3, e2));
        }

        // O += P V
        #pragma unroll
        for (int f = 0; f < 4; f++) {
            #pragma unroll
            for (int ks = 0; ks < 4; ks++) {
                unsigned d0, d1, d2, d3;
                ldsm4(d0, d1, d2, d3,
                      sptr(&Vf[(16 * f + lrow8) * KP + 8 * ks + lsel]));
                mma16(O[2*f],   ph[2*ks], phh[2*ks], ph[2*ks+1], phh[2*ks+1], d0, d1);
                mma16(O[2*f+1], ph[2*ks], phh[2*ks], ph[2*ks+1], phh[2*ks+1], d2, d3);
            }
        }
        #pragma unroll
        for (int ks = 0; ks < 4; ks++)
            mma16(O8, ph[2*ks], phh[2*ks], ph[2*ks+1], phh[2*ks+1], ones2, ones2);

        // publish next tile's kq (ordered by next iteration's top barrier)
        if (pref && tid < 64)
            kq[(buf ^ 1) * 64 + tid] =
                make_float4(pp.x, pp.y, nc2 * (pp.x * pp.x + pp.y * pp.y), 0.f);
    }

    // l from t=0 lane of each quad; normalize; write g_ao PLAIN
    float l0 = __shfl_sync(0xffffffffu, O8[0], lane & ~3);
    float l1 = __shfl_sync(0xffffffffu, O8[2], lane & ~3);
    float il0 = 1.f / l0, il1 = 1.f / l1;
    int r0 = i0 + wr + g, r1 = r0 + 8;
    #pragma unroll
    for (int df = 0; df < 8; df++) {
        int col = df * 4 + t;                         // uint within head block
        g_ao[(size_t)(b * L_ + r0) * D2 + h * 32 + col] = pk2(O[df][0] * il0, O[df][1] * il0);
        g_ao[(size_t)(b * L_ + r1) * D2 + h * 32 + col] = pk2(O[df][2] * il1, O[df][3] * il1);
    }
}

// ---------------------------------------------------------------------------
extern "C" void kernel_launch(void* const* d_in, const int* in_sizes, int n_in,
                              void* d_out, int out_size)
{
    const float* x     = (const float*)d_in[0];
    const float* pos   = (const float*)d_in[1];
    const float* wqkv  = (const float*)d_in[2];
    const float* wout  = (const float*)d_in[3];
    const float* bout  = (const float*)d_in[4];
    const float* lsig  = (const float*)d_in[5];
    const float* gbias = (const float*)d_in[6];
    const int*   nsp   = (const int*)d_in[7];
    float* out = (float*)d_out;

    unsigned *p_xt, *p_w1, *p_w2;
    cudaGetSymbolAddress((void**)&p_xt, g_xt);
    cudaGetSymbolAddress((void**)&p_w1, g_w1);
    cudaGetSymbolAddress((void**)&p_w2, g_w2);

    cudaFuncSetAttribute(attn_h, cudaFuncAttributeMaxDynamicSharedMemorySize, ATTN_SMEM);
    cudaFuncSetAttribute(gemm_h<NQKV, 0>, cudaFuncAttributeMaxDynamicSharedMemorySize, GEMM_SMEM);
    cudaFuncSetAttribute(gemm_h<D_, 1>, cudaFuncAttributeMaxDynamicSharedMemorySize, GEMM_SMEM);

    prep_all<<<(N16_TOT + 255) / 256, 256>>>(x, wqkv, wout);
    gemm_h<NQKV, 0><<<dim3(NQKV / 128, M_ / 128), 256, GEMM_SMEM>>>(p_xt, p_w1, nullptr, nullptr);
    attn_h<<<dim3(L_ / 128, B_ * H_), 256, ATTN_SMEM>>>(pos, lsig, gbias, nsp);
    gemm_h<D_, 1><<<dim3(D_ / 128, M_ / 128), 256, GEMM_SMEM>>>(nullptr, p_w2, bout, out);
}